// round 10
// baseline (speedup 1.0000x reference)
#include <cuda_runtime.h>
#include <cuda_fp16.h>
#include <cstdint>

// GraphSAGE 2-layer encoder.
//   y = h@Wl (fp16), z = h@Wr + b (fp32), out[i] = inv[i]*sum_{j in N(i)} y[j] + z[i]
// HMMA GEMMs; layer-1 GEMM overlapped with CSR histogram; wide-load gathers
// with fp16 pair-tree + packed f32x2 accumulation (sm_103a).

#define NMAX 100000
#define EMAX 1600000
#define F 64
#define TS 72   // smem row stride in halves (144B, 16B-aligned rows)

__device__ __align__(16) __half g_ya[NMAX * F];
__device__ __align__(16) __half g_yb[NMAX * F];
__device__ __align__(16) float  g_z1[NMAX * F];
__device__ __align__(16) float  g_z2[NMAX * F];
__device__ float g_invdeg[NMAX];
__device__ int   g_cnt[NMAX];        // zero-init at load; re-zeroed by k_agg2
__device__ int   g_rowptr[NMAX];
__device__ int   g_rowend[NMAX];
__device__ int   g_pos[EMAX];
__device__ int   g_col[EMAX];
__device__ int   g_ctr;              // chunk-base counter (re-zeroed by k_agg2)

// ---------------------------------------------------------------- MMA bits
__device__ __forceinline__ unsigned smem_u32(const void* p) {
    return (unsigned)__cvta_generic_to_shared(p);
}
__device__ __forceinline__ void ldsm_x4(unsigned& a0, unsigned& a1,
                                        unsigned& a2, unsigned& a3, unsigned addr) {
    asm volatile("ldmatrix.sync.aligned.m8n8.x4.shared.b16 {%0,%1,%2,%3}, [%4];"
                 : "=r"(a0), "=r"(a1), "=r"(a2), "=r"(a3) : "r"(addr));
}
__device__ __forceinline__ void ldsm_x2t(unsigned& b0, unsigned& b1, unsigned addr) {
    asm volatile("ldmatrix.sync.aligned.m8n8.x2.trans.shared.b16 {%0,%1}, [%2];"
                 : "=r"(b0), "=r"(b1) : "r"(addr));
}
__device__ __forceinline__ void mma16816(float* d, unsigned a0, unsigned a1,
                                         unsigned a2, unsigned a3,
                                         unsigned b0, unsigned b1) {
    asm volatile("mma.sync.aligned.m16n8k16.row.col.f32.f16.f16.f32 "
                 "{%0,%1,%2,%3}, {%4,%5,%6,%7}, {%8,%9}, {%0,%1,%2,%3};"
                 : "+f"(d[0]), "+f"(d[1]), "+f"(d[2]), "+f"(d[3])
                 : "r"(a0), "r"(a1), "r"(a2), "r"(a3), "r"(b0), "r"(b1));
}

// Dual GEMM on a 64-row tile: Y = A@Wl (fp16 out), Z = A@Wr + b (fp32 out).
__device__ __forceinline__ void mma_dual(const __half* xs, const __half* wls,
                                         const __half* wrs, const float* bs,
                                         __half* Yg, float* Zg, int row0, int n,
                                         int tid) {
    int w = tid >> 5, l = tid & 31;
    int m0 = (w & 3) * 16;
    int nb = (w >> 2) * 32;

    float acc0[4][4], acc1[4][4];
    #pragma unroll
    for (int j = 0; j < 4; ++j)
        #pragma unroll
        for (int q = 0; q < 4; ++q) { acc0[j][q] = 0.f; acc1[j][q] = 0.f; }

    int ag = l >> 3, ar = l & 7;
    int arow = m0 + (ag & 1) * 8 + ar;
    int acol = (ag >> 1) * 8;
    int br   = (l & 7) + ((l >> 3) & 1) * 8;

    #pragma unroll
    for (int kc = 0; kc < 4; ++kc) {
        int k0 = kc * 16;
        unsigned a0, a1, a2, a3;
        ldsm_x4(a0, a1, a2, a3, smem_u32(&xs[arow * TS + k0 + acol]));
        #pragma unroll
        for (int j = 0; j < 4; ++j) {
            int n0 = nb + j * 8;
            unsigned b0, b1, c0, c1;
            ldsm_x2t(b0, b1, smem_u32(&wls[(k0 + br) * TS + n0]));
            mma16816(acc0[j], a0, a1, a2, a3, b0, b1);
            ldsm_x2t(c0, c1, smem_u32(&wrs[(k0 + br) * TS + n0]));
            mma16816(acc1[j], a0, a1, a2, a3, c0, c1);
        }
    }

    int tr = l >> 2, tc = (l & 3) * 2;
    #pragma unroll
    for (int j = 0; j < 4; ++j) {
        int gc = nb + j * 8 + tc;
        float bx = bs[gc], by = bs[gc + 1];
        #pragma unroll
        for (int h = 0; h < 2; ++h) {
            int gr = row0 + m0 + tr + h * 8;
            if (gr < n) {
                *(__half2*)&Yg[gr * 64 + gc] =
                    __floats2half2_rn(acc0[j][h * 2], acc0[j][h * 2 + 1]);
                *(float2*)&Zg[gr * 64 + gc] =
                    make_float2(acc1[j][h * 2] + bx, acc1[j][h * 2 + 1] + by);
            }
        }
    }
}

// packed f32x2 helpers (sm_103a dual-rate fp32 add; PTX-only)
__device__ __forceinline__ void acc_f32x2(unsigned long long& p, float2 f) {
    unsigned long long ff;
    asm("mov.b64 %0, {%1, %2};" : "=l"(ff) : "f"(f.x), "f"(f.y));
    asm("add.rn.f32x2 %0, %0, %1;" : "+l"(p) : "l"(ff));
}

// Warp-cooperative gather: lane = (g = l>>3 edge subgroup, s = l&7 dim chunk).
// Each lane loads float4 (16B) of the y-row; 4 edges per warp-step; 16 edges
// in flight. The 4 in-flight edges are pair-tree reduced in fp16 (HADD2),
// then accumulated packed-fp32. Full row sum lands in acc[8] of all lanes.
__device__ __forceinline__ void gather_row(const float4* Y, int i0, int e,
                                           int g, int s, float* acc) {
    unsigned long long p[4];
    p[0] = 0ull; p[1] = 0ull; p[2] = 0ull; p[3] = 0ull;
    int i = i0 + g;
    for (; i + 12 < e; i += 16) {
        float4 v0 = Y[g_col[i]      * 8 + s];
        float4 v1 = Y[g_col[i + 4]  * 8 + s];
        float4 v2 = Y[g_col[i + 8]  * 8 + s];
        float4 v3 = Y[g_col[i + 12] * 8 + s];
        __half2* h0 = (__half2*)&v0;
        __half2* h1 = (__half2*)&v1;
        __half2* h2 = (__half2*)&v2;
        __half2* h3 = (__half2*)&v3;
        #pragma unroll
        for (int k = 0; k < 4; ++k) {
            __half2 w = __hadd2(__hadd2(h0[k], h1[k]), __hadd2(h2[k], h3[k]));
            acc_f32x2(p[k], __half22float2(w));
        }
    }
    for (; i < e; i += 4) {
        float4 v = Y[g_col[i] * 8 + s];
        __half2* h = (__half2*)&v;
        #pragma unroll
        for (int k = 0; k < 4; ++k)
            acc_f32x2(p[k], __half22float2(h[k]));
    }
    #pragma unroll
    for (int k = 0; k < 4; ++k)
        asm("mov.b64 {%0, %1}, %2;" : "=f"(acc[2*k]), "=f"(acc[2*k+1]) : "l"(p[k]));
    __syncwarp();
    #pragma unroll
    for (int d = 0; d < 8; ++d) {
        acc[d] += __shfl_xor_sync(0xffffffffu, acc[d], 8);
        acc[d] += __shfl_xor_sync(0xffffffffu, acc[d], 16);
    }
}

// ------------------------------ fused histogram (CSR pass 1) + layer-1 GEMM
__global__ __launch_bounds__(256) void k_histgemm(const int* __restrict__ dst, int E, int HB,
                                                  const float* __restrict__ X,
                                                  const float* __restrict__ Wl,
                                                  const float* __restrict__ Wr,
                                                  const float* __restrict__ B,
                                                  int n) {
    if (blockIdx.x < (unsigned)HB) {
        int t  = blockIdx.x * 256 + threadIdx.x;
        int e4 = t * 4;
        if (e4 >= E) return;
        if (((E & 3) == 0) && e4 + 3 < E) {
            int4 d4 = ((const int4*)dst)[t];
            g_pos[e4 + 0] = atomicAdd(&g_cnt[d4.x], 1);
            g_pos[e4 + 1] = atomicAdd(&g_cnt[d4.y], 1);
            g_pos[e4 + 2] = atomicAdd(&g_cnt[d4.z], 1);
            g_pos[e4 + 3] = atomicAdd(&g_cnt[d4.w], 1);
        } else {
            int lim = min(e4 + 4, E);
            for (int e = e4; e < lim; ++e)
                g_pos[e] = atomicAdd(&g_cnt[dst[e]], 1);
        }
        return;
    }

    __shared__ __half xs[64 * TS];
    __shared__ __half wls[64 * TS];
    __shared__ __half wrs[64 * TS];
    __shared__ float  bs[64];

    int tid  = threadIdx.x;
    int row0 = ((int)blockIdx.x - HB) * 64;

    for (int t = tid; t < 1024; t += 256) {
        int r = t >> 4, c4 = (t & 15) << 2;
        float4 wl = ((const float4*)Wl)[t];
        float4 wr = ((const float4*)Wr)[t];
        *(__half2*)&wls[r * TS + c4]     = __floats2half2_rn(wl.x, wl.y);
        *(__half2*)&wls[r * TS + c4 + 2] = __floats2half2_rn(wl.z, wl.w);
        *(__half2*)&wrs[r * TS + c4]     = __floats2half2_rn(wr.x, wr.y);
        *(__half2*)&wrs[r * TS + c4 + 2] = __floats2half2_rn(wr.z, wr.w);

        int g = row0 + r;
        float4 v = make_float4(0.f, 0.f, 0.f, 0.f);
        if (g < n) v = *(const float4*)&X[g * 64 + c4];
        *(__half2*)&xs[r * TS + c4]     = __floats2half2_rn(v.x, v.y);
        *(__half2*)&xs[r * TS + c4 + 2] = __floats2half2_rn(v.z, v.w);
    }
    if (tid < 64) bs[tid] = B[tid];
    __syncthreads();

    mma_dual(xs, wls, wrs, bs, g_ya, g_z1, row0, n, tid);
}

// single-pass CSR scan: local chunk scan + atomic global base
__global__ void k_scan(int n) {
    __shared__ int sh[1024];
    __shared__ int base_sh;
    int tid = threadIdx.x;
    int i = blockIdx.x * 1024 + tid;
    int v = (i < n) ? g_cnt[i] : 0;
    sh[tid] = v;
    __syncthreads();
    #pragma unroll
    for (int off = 1; off < 1024; off <<= 1) {
        int t = (tid >= off) ? sh[tid - off] : 0;
        __syncthreads();
        sh[tid] += t;
        __syncthreads();
    }
    if (tid == 1023) base_sh = atomicAdd(&g_ctr, sh[1023]);
    __syncthreads();
    if (i < n) {
        int base = base_sh;
        int incl = sh[tid];
        g_rowptr[i] = base + incl - v;
        g_rowend[i] = base + incl;
        g_invdeg[i] = 1.0f / (float)max(v, 1);
    }
}

// atomic-free scatter, 4 edges/thread
__global__ void k_scatter(const int* __restrict__ src, const int* __restrict__ dst, int E) {
    int t  = blockIdx.x * blockDim.x + threadIdx.x;
    int e4 = t * 4;
    if (e4 >= E) return;
    if (((E & 3) == 0) && e4 + 3 < E) {
        int4 d4 = ((const int4*)dst)[t];
        int4 p4 = ((const int4*)g_pos)[t];
        int4 s4 = ((const int4*)src)[t];
        g_col[g_rowptr[d4.x] + p4.x] = s4.x;
        g_col[g_rowptr[d4.y] + p4.y] = s4.y;
        g_col[g_rowptr[d4.z] + p4.z] = s4.z;
        g_col[g_rowptr[d4.w] + p4.w] = s4.w;
    } else {
        int lim = min(e4 + 4, E);
        for (int e = e4; e < lim; ++e)
            g_col[g_rowptr[dst[e]] + g_pos[e]] = src[e];
    }
}

// -------------------------------- fused layer-1 aggregate + layer-2 GEMM
__global__ __launch_bounds__(256) void k_fused(const float* __restrict__ Wl,
                                               const float* __restrict__ Wr,
                                               const float* __restrict__ B,
                                               int n) {
    __shared__ __half xs[64 * TS];
    __shared__ __half wls[64 * TS];
    __shared__ __half wrs[64 * TS];
    __shared__ float  bs[64];

    int tid  = threadIdx.x;
    int row0 = blockIdx.x * 64;
    int lane = tid & 31, w = tid >> 5;
    int g = lane >> 3, s = lane & 7;

    for (int t = tid; t < 1024; t += 256) {
        int r = t >> 4, c4 = (t & 15) << 2;
        float4 wl = ((const float4*)Wl)[t];
        float4 wr = ((const float4*)Wr)[t];
        *(__half2*)&wls[r * TS + c4]     = __floats2half2_rn(wl.x, wl.y);
        *(__half2*)&wls[r * TS + c4 + 2] = __floats2half2_rn(wl.z, wl.w);
        *(__half2*)&wrs[r * TS + c4]     = __floats2half2_rn(wr.x, wr.y);
        *(__half2*)&wrs[r * TS + c4 + 2] = __floats2half2_rn(wr.z, wr.w);
    }
    if (tid < 64) bs[tid] = B[tid];

    // phase 1: warp per node; 8 passes cover 64 rows
    const float4* Y = (const float4*)g_ya;
    #pragma unroll 1
    for (int pass = 0; pass < 8; ++pass) {
        int nl   = pass * 8 + w;
        int node = row0 + nl;
        float acc[8];
        int i0 = 0, e = 0;
        if (node < n) { i0 = g_rowptr[node]; e = g_rowend[node]; }
        gather_row(Y, i0, e, g, s, acc);
        if (g == 0) {
            __half2 hh[4];
            if (node < n) {
                float inv = g_invdeg[node];
                const float4* Z = (const float4*)g_z1;
                float4 z0 = Z[node * 16 + s * 2];
                float4 z1 = Z[node * 16 + s * 2 + 1];
                hh[0] = __floats2half2_rn(fmaxf(acc[0]*inv + z0.x, 0.f),
                                          fmaxf(acc[1]*inv + z0.y, 0.f));
                hh[1] = __floats2half2_rn(fmaxf(acc[2]*inv + z0.z, 0.f),
                                          fmaxf(acc[3]*inv + z0.w, 0.f));
                hh[2] = __floats2half2_rn(fmaxf(acc[4]*inv + z1.x, 0.f),
                                          fmaxf(acc[5]*inv + z1.y, 0.f));
                hh[3] = __floats2half2_rn(fmaxf(acc[6]*inv + z1.z, 0.f),
                                          fmaxf(acc[7]*inv + z1.w, 0.f));
            } else {
                hh[0] = hh[1] = hh[2] = hh[3] = __floats2half2_rn(0.f, 0.f);
            }
            *(float4*)&xs[nl * TS + s * 8] = *(float4*)hh;
        }
    }
    __syncthreads();

    mma_dual(xs, wls, wrs, bs, g_yb, g_z2, row0, n, tid);
}

// --------------------------------------------------------- final aggregate
__global__ __launch_bounds__(256) void k_agg2(float* __restrict__ Og, int n) {
    int tid  = threadIdx.x;
    int lane = tid & 31, w = tid >> 5;
    int node = blockIdx.x * 8 + w;
    int g = lane >> 3, s = lane & 7;

    if (tid < 8) {
        int nn = blockIdx.x * 8 + tid;
        if (nn < n) g_cnt[nn] = 0;      // counters clean for next graph replay
    }
    if (blockIdx.x == 0 && tid == 0) g_ctr = 0;
    if (node >= n) return;

    const float4* Y = (const float4*)g_yb;
    float acc[8];
    gather_row(Y, g_rowptr[node], g_rowend[node], g, s, acc);

    if (g == 0) {
        float inv = g_invdeg[node];
        const float4* Z = (const float4*)g_z2;
        float4 z0 = Z[node * 16 + s * 2];
        float4 z1 = Z[node * 16 + s * 2 + 1];
        float4 o0 = make_float4(acc[0]*inv + z0.x, acc[1]*inv + z0.y,
                                acc[2]*inv + z0.z, acc[3]*inv + z0.w);
        float4 o1 = make_float4(acc[4]*inv + z1.x, acc[5]*inv + z1.y,
                                acc[6]*inv + z1.z, acc[7]*inv + z1.w);
        *(float4*)&Og[node * 64 + s * 8]     = o0;
        *(float4*)&Og[node * 64 + s * 8 + 4] = o1;
    }
}

// ------------------------------------------------------------------- launch
extern "C" void kernel_launch(void* const* d_in, const int* in_sizes, int n_in,
                              void* d_out, int out_size) {
    const float* x   = (const float*)d_in[0];
    const int*   ei  = (const int*)d_in[1];
    const float* w1l = (const float*)d_in[2];
    const float* b1l = (const float*)d_in[3];
    const float* w1r = (const float*)d_in[4];
    const float* w2l = (const float*)d_in[5];
    const float* b2l = (const float*)d_in[6];
    const float* w2r = (const float*)d_in[7];
    float* out = (float*)d_out;

    int n = in_sizes[0] / F;
    int E = in_sizes[1] / 2;
    const int* src = ei;
    const int* dst = ei + E;

    int HB = (E + 1023) / 1024;          // hist blocks (4 edges/thread)
    int GB = (n + 63) / 64;              // gemm blocks

    k_histgemm<<<HB + GB, 256>>>(dst, E, HB, x, w1l, w1r, b1l, n);
    k_scan    <<<(n + 1023) / 1024, 1024>>>(n);
    k_scatter <<<(E / 4 + 255) / 256, 256>>>(src, dst, E);

    k_fused <<<GB, 256>>>(w2l, w2r, b2l, n);
    k_agg2  <<<(n + 7) / 8, 256>>>(out, n);
}

// round 11
// speedup vs baseline: 1.0461x; 1.0461x over previous
#include <cuda_runtime.h>
#include <cuda_fp16.h>
#include <cstdint>

// GraphSAGE 2-layer encoder.
//   y = h@Wl (fp16), z = h@Wr + b (fp32), out[i] = inv[i]*sum_{j in N(i)} y[j] + z[i]
// HMMA GEMMs; layer-1 GEMM overlapped with CSR histogram; dual-node
// interleaved gathers (2 independent load chains per warp).

#define NMAX 100000
#define EMAX 1600000
#define F 64
#define TS 72   // smem row stride in halves (144B, 16B-aligned rows)

__device__ __align__(16) __half g_ya[NMAX * F];
__device__ __align__(16) __half g_yb[NMAX * F];
__device__ __align__(16) float  g_z1[NMAX * F];
__device__ __align__(16) float  g_z2[NMAX * F];
__device__ float g_invdeg[NMAX];
__device__ int   g_cnt[NMAX];        // zero-init at load; re-zeroed by k_agg2
__device__ int   g_rowptr[NMAX];
__device__ int   g_rowend[NMAX];
__device__ int   g_pos[EMAX];
__device__ int   g_col[EMAX];
__device__ int   g_ctr;              // chunk-base counter (re-zeroed by k_agg2)

// ---------------------------------------------------------------- MMA bits
__device__ __forceinline__ unsigned smem_u32(const void* p) {
    return (unsigned)__cvta_generic_to_shared(p);
}
__device__ __forceinline__ void ldsm_x4(unsigned& a0, unsigned& a1,
                                        unsigned& a2, unsigned& a3, unsigned addr) {
    asm volatile("ldmatrix.sync.aligned.m8n8.x4.shared.b16 {%0,%1,%2,%3}, [%4];"
                 : "=r"(a0), "=r"(a1), "=r"(a2), "=r"(a3) : "r"(addr));
}
__device__ __forceinline__ void ldsm_x2t(unsigned& b0, unsigned& b1, unsigned addr) {
    asm volatile("ldmatrix.sync.aligned.m8n8.x2.trans.shared.b16 {%0,%1}, [%2];"
                 : "=r"(b0), "=r"(b1) : "r"(addr));
}
__device__ __forceinline__ void mma16816(float* d, unsigned a0, unsigned a1,
                                         unsigned a2, unsigned a3,
                                         unsigned b0, unsigned b1) {
    asm volatile("mma.sync.aligned.m16n8k16.row.col.f32.f16.f16.f32 "
                 "{%0,%1,%2,%3}, {%4,%5,%6,%7}, {%8,%9}, {%0,%1,%2,%3};"
                 : "+f"(d[0]), "+f"(d[1]), "+f"(d[2]), "+f"(d[3])
                 : "r"(a0), "r"(a1), "r"(a2), "r"(a3), "r"(b0), "r"(b1));
}

// Dual GEMM on a 64-row tile: Y = A@Wl (fp16 out), Z = A@Wr + b (fp32 out).
__device__ __forceinline__ void mma_dual(const __half* xs, const __half* wls,
                                         const __half* wrs, const float* bs,
                                         __half* Yg, float* Zg, int row0, int n,
                                         int tid) {
    int w = tid >> 5, l = tid & 31;
    int m0 = (w & 3) * 16;
    int nb = (w >> 2) * 32;

    float acc0[4][4], acc1[4][4];
    #pragma unroll
    for (int j = 0; j < 4; ++j)
        #pragma unroll
        for (int q = 0; q < 4; ++q) { acc0[j][q] = 0.f; acc1[j][q] = 0.f; }

    int ag = l >> 3, ar = l & 7;
    int arow = m0 + (ag & 1) * 8 + ar;
    int acol = (ag >> 1) * 8;
    int br   = (l & 7) + ((l >> 3) & 1) * 8;

    #pragma unroll
    for (int kc = 0; kc < 4; ++kc) {
        int k0 = kc * 16;
        unsigned a0, a1, a2, a3;
        ldsm_x4(a0, a1, a2, a3, smem_u32(&xs[arow * TS + k0 + acol]));
        #pragma unroll
        for (int j = 0; j < 4; ++j) {
            int n0 = nb + j * 8;
            unsigned b0, b1, c0, c1;
            ldsm_x2t(b0, b1, smem_u32(&wls[(k0 + br) * TS + n0]));
            mma16816(acc0[j], a0, a1, a2, a3, b0, b1);
            ldsm_x2t(c0, c1, smem_u32(&wrs[(k0 + br) * TS + n0]));
            mma16816(acc1[j], a0, a1, a2, a3, c0, c1);
        }
    }

    int tr = l >> 2, tc = (l & 3) * 2;
    #pragma unroll
    for (int j = 0; j < 4; ++j) {
        int gc = nb + j * 8 + tc;
        float bx = bs[gc], by = bs[gc + 1];
        #pragma unroll
        for (int h = 0; h < 2; ++h) {
            int gr = row0 + m0 + tr + h * 8;
            if (gr < n) {
                *(__half2*)&Yg[gr * 64 + gc] =
                    __floats2half2_rn(acc0[j][h * 2], acc0[j][h * 2 + 1]);
                *(float2*)&Zg[gr * 64 + gc] =
                    make_float2(acc1[j][h * 2] + bx, acc1[j][h * 2 + 1] + by);
            }
        }
    }
}

// accumulate 8 halves (one float4) into 8 fp32 accumulators
__device__ __forceinline__ void add8(float* acc, float4 v) {
    __half2* h = (__half2*)&v;
    #pragma unroll
    for (int k = 0; k < 4; ++k) {
        float2 f = __half22float2(h[k]);
        acc[2 * k]     += f.x;
        acc[2 * k + 1] += f.y;
    }
}

// Dual-node warp-cooperative gather. lane = (g = l>>3 edge subgroup,
// s = l&7 dim chunk). Two independent ranges [iA,eA) and [iB,eB) are walked
// concurrently so each lane keeps up to 8 LDG.128 in flight across 2 chains.
// Row sums land in accA[8]/accB[8] on all lanes after the shfl reduce.
__device__ __forceinline__ void gather2(const float4* __restrict__ Y,
                                        int iA, int eA, int iB, int eB,
                                        int g, int s, float* accA, float* accB) {
    #pragma unroll
    for (int d = 0; d < 8; ++d) { accA[d] = 0.f; accB[d] = 0.f; }
    iA += g; iB += g;

    // joint main loop: 16 edges per node per iteration, 8 loads/lane in flight
    while (iA + 12 < eA && iB + 12 < eB) {
        float4 a0 = Y[g_col[iA]      * 8 + s];
        float4 a1 = Y[g_col[iA + 4]  * 8 + s];
        float4 a2 = Y[g_col[iA + 8]  * 8 + s];
        float4 a3 = Y[g_col[iA + 12] * 8 + s];
        float4 b0 = Y[g_col[iB]      * 8 + s];
        float4 b1 = Y[g_col[iB + 4]  * 8 + s];
        float4 b2 = Y[g_col[iB + 8]  * 8 + s];
        float4 b3 = Y[g_col[iB + 12] * 8 + s];
        add8(accA, a0); add8(accA, a1); add8(accA, a2); add8(accA, a3);
        add8(accB, b0); add8(accB, b1); add8(accB, b2); add8(accB, b3);
        iA += 16; iB += 16;
    }
    // leftover main loops (lengths differ by >16 — rare)
    while (iA + 12 < eA) {
        float4 a0 = Y[g_col[iA]      * 8 + s];
        float4 a1 = Y[g_col[iA + 4]  * 8 + s];
        float4 a2 = Y[g_col[iA + 8]  * 8 + s];
        float4 a3 = Y[g_col[iA + 12] * 8 + s];
        add8(accA, a0); add8(accA, a1); add8(accA, a2); add8(accA, a3);
        iA += 16;
    }
    while (iB + 12 < eB) {
        float4 b0 = Y[g_col[iB]      * 8 + s];
        float4 b1 = Y[g_col[iB + 4]  * 8 + s];
        float4 b2 = Y[g_col[iB + 8]  * 8 + s];
        float4 b3 = Y[g_col[iB + 12] * 8 + s];
        add8(accB, b0); add8(accB, b1); add8(accB, b2); add8(accB, b3);
        iB += 16;
    }
    // joint predicated tail: both chains stay live
    while (iA < eA || iB < eB) {
        bool a = iA < eA, b = iB < eB;
        float4 va, vb;
        if (a) va = Y[g_col[iA] * 8 + s];
        if (b) vb = Y[g_col[iB] * 8 + s];
        if (a) { add8(accA, va); iA += 4; }
        if (b) { add8(accB, vb); iB += 4; }
    }

    __syncwarp();
    #pragma unroll
    for (int d = 0; d < 8; ++d) {
        accA[d] += __shfl_xor_sync(0xffffffffu, accA[d], 8);
        accA[d] += __shfl_xor_sync(0xffffffffu, accA[d], 16);
        accB[d] += __shfl_xor_sync(0xffffffffu, accB[d], 8);
        accB[d] += __shfl_xor_sync(0xffffffffu, accB[d], 16);
    }
}

// ------------------------------ fused histogram (CSR pass 1) + layer-1 GEMM
__global__ __launch_bounds__(256) void k_histgemm(const int* __restrict__ dst, int E, int HB,
                                                  const float* __restrict__ X,
                                                  const float* __restrict__ Wl,
                                                  const float* __restrict__ Wr,
                                                  const float* __restrict__ B,
                                                  int n) {
    if (blockIdx.x < (unsigned)HB) {
        int t  = blockIdx.x * 256 + threadIdx.x;
        int e4 = t * 4;
        if (e4 >= E) return;
        if (((E & 3) == 0) && e4 + 3 < E) {
            int4 d4 = ((const int4*)dst)[t];
            g_pos[e4 + 0] = atomicAdd(&g_cnt[d4.x], 1);
            g_pos[e4 + 1] = atomicAdd(&g_cnt[d4.y], 1);
            g_pos[e4 + 2] = atomicAdd(&g_cnt[d4.z], 1);
            g_pos[e4 + 3] = atomicAdd(&g_cnt[d4.w], 1);
        } else {
            int lim = min(e4 + 4, E);
            for (int e = e4; e < lim; ++e)
                g_pos[e] = atomicAdd(&g_cnt[dst[e]], 1);
        }
        return;
    }

    __shared__ __half xs[64 * TS];
    __shared__ __half wls[64 * TS];
    __shared__ __half wrs[64 * TS];
    __shared__ float  bs[64];

    int tid  = threadIdx.x;
    int row0 = ((int)blockIdx.x - HB) * 64;

    for (int t = tid; t < 1024; t += 256) {
        int r = t >> 4, c4 = (t & 15) << 2;
        float4 wl = ((const float4*)Wl)[t];
        float4 wr = ((const float4*)Wr)[t];
        *(__half2*)&wls[r * TS + c4]     = __floats2half2_rn(wl.x, wl.y);
        *(__half2*)&wls[r * TS + c4 + 2] = __floats2half2_rn(wl.z, wl.w);
        *(__half2*)&wrs[r * TS + c4]     = __floats2half2_rn(wr.x, wr.y);
        *(__half2*)&wrs[r * TS + c4 + 2] = __floats2half2_rn(wr.z, wr.w);

        int g = row0 + r;
        float4 v = make_float4(0.f, 0.f, 0.f, 0.f);
        if (g < n) v = *(const float4*)&X[g * 64 + c4];
        *(__half2*)&xs[r * TS + c4]     = __floats2half2_rn(v.x, v.y);
        *(__half2*)&xs[r * TS + c4 + 2] = __floats2half2_rn(v.z, v.w);
    }
    if (tid < 64) bs[tid] = B[tid];
    __syncthreads();

    mma_dual(xs, wls, wrs, bs, g_ya, g_z1, row0, n, tid);
}

// single-pass CSR scan: local chunk scan + atomic global base
__global__ void k_scan(int n) {
    __shared__ int sh[1024];
    __shared__ int base_sh;
    int tid = threadIdx.x;
    int i = blockIdx.x * 1024 + tid;
    int v = (i < n) ? g_cnt[i] : 0;
    sh[tid] = v;
    __syncthreads();
    #pragma unroll
    for (int off = 1; off < 1024; off <<= 1) {
        int t = (tid >= off) ? sh[tid - off] : 0;
        __syncthreads();
        sh[tid] += t;
        __syncthreads();
    }
    if (tid == 1023) base_sh = atomicAdd(&g_ctr, sh[1023]);
    __syncthreads();
    if (i < n) {
        int base = base_sh;
        int incl = sh[tid];
        g_rowptr[i] = base + incl - v;
        g_rowend[i] = base + incl;
        g_invdeg[i] = 1.0f / (float)max(v, 1);
    }
}

// atomic-free scatter, 4 edges/thread
__global__ void k_scatter(const int* __restrict__ src, const int* __restrict__ dst, int E) {
    int t  = blockIdx.x * blockDim.x + threadIdx.x;
    int e4 = t * 4;
    if (e4 >= E) return;
    if (((E & 3) == 0) && e4 + 3 < E) {
        int4 d4 = ((const int4*)dst)[t];
        int4 p4 = ((const int4*)g_pos)[t];
        int4 s4 = ((const int4*)src)[t];
        g_col[g_rowptr[d4.x] + p4.x] = s4.x;
        g_col[g_rowptr[d4.y] + p4.y] = s4.y;
        g_col[g_rowptr[d4.z] + p4.z] = s4.z;
        g_col[g_rowptr[d4.w] + p4.w] = s4.w;
    } else {
        int lim = min(e4 + 4, E);
        for (int e = e4; e < lim; ++e)
            g_col[g_rowptr[dst[e]] + g_pos[e]] = src[e];
    }
}

// -------------------------------- fused layer-1 aggregate + layer-2 GEMM
__global__ __launch_bounds__(256) void k_fused(const float* __restrict__ Wl,
                                               const float* __restrict__ Wr,
                                               const float* __restrict__ B,
                                               int n) {
    __shared__ __half xs[64 * TS];
    __shared__ __half wls[64 * TS];
    __shared__ __half wrs[64 * TS];
    __shared__ float  bs[64];

    int tid  = threadIdx.x;
    int row0 = blockIdx.x * 64;
    int lane = tid & 31, w = tid >> 5;
    int g = lane >> 3, s = lane & 7;

    for (int t = tid; t < 1024; t += 256) {
        int r = t >> 4, c4 = (t & 15) << 2;
        float4 wl = ((const float4*)Wl)[t];
        float4 wr = ((const float4*)Wr)[t];
        *(__half2*)&wls[r * TS + c4]     = __floats2half2_rn(wl.x, wl.y);
        *(__half2*)&wls[r * TS + c4 + 2] = __floats2half2_rn(wl.z, wl.w);
        *(__half2*)&wrs[r * TS + c4]     = __floats2half2_rn(wr.x, wr.y);
        *(__half2*)&wrs[r * TS + c4 + 2] = __floats2half2_rn(wr.z, wr.w);
    }
    if (tid < 64) bs[tid] = B[tid];

    // phase 1: warp handles 2 nodes per pass (rows p*8+w and p*8+w+32)
    const float4* Y = (const float4*)g_ya;
    #pragma unroll 1
    for (int pass = 0; pass < 4; ++pass) {
        int nlA = pass * 8 + w;
        int nlB = nlA + 32;
        int nodeA = row0 + nlA, nodeB = row0 + nlB;
        int iA = 0, eA = 0, iB = 0, eB = 0;
        if (nodeA < n) { iA = g_rowptr[nodeA]; eA = g_rowend[nodeA]; }
        if (nodeB < n) { iB = g_rowptr[nodeB]; eB = g_rowend[nodeB]; }
        float accA[8], accB[8];
        gather2(Y, iA, eA, iB, eB, g, s, accA, accB);
        if (g == 0) {
            const float4* Z = (const float4*)g_z1;
            __half2 hh[4];
            #pragma unroll
            for (int half_ = 0; half_ < 2; ++half_) {
                int node = half_ ? nodeB : nodeA;
                int nl   = half_ ? nlB : nlA;
                float* acc = half_ ? accB : accA;
                if (node < n) {
                    float inv = g_invdeg[node];
                    float4 z0 = Z[node * 16 + s * 2];
                    float4 z1 = Z[node * 16 + s * 2 + 1];
                    hh[0] = __floats2half2_rn(fmaxf(acc[0]*inv + z0.x, 0.f),
                                              fmaxf(acc[1]*inv + z0.y, 0.f));
                    hh[1] = __floats2half2_rn(fmaxf(acc[2]*inv + z0.z, 0.f),
                                              fmaxf(acc[3]*inv + z0.w, 0.f));
                    hh[2] = __floats2half2_rn(fmaxf(acc[4]*inv + z1.x, 0.f),
                                              fmaxf(acc[5]*inv + z1.y, 0.f));
                    hh[3] = __floats2half2_rn(fmaxf(acc[6]*inv + z1.z, 0.f),
                                              fmaxf(acc[7]*inv + z1.w, 0.f));
                } else {
                    hh[0] = hh[1] = hh[2] = hh[3] = __floats2half2_rn(0.f, 0.f);
                }
                *(float4*)&xs[nl * TS + s * 8] = *(float4*)hh;
            }
        }
    }
    __syncthreads();

    mma_dual(xs, wls, wrs, bs, g_yb, g_z2, row0, n, tid);
}

// --------------------------------------------------------- final aggregate
// 16 nodes per block: warp w handles nodes base+w and base+w+8.
__global__ __launch_bounds__(256) void k_agg2(float* __restrict__ Og, int n) {
    int tid  = threadIdx.x;
    int lane = tid & 31, w = tid >> 5;
    int base = blockIdx.x * 16;
    int nodeA = base + w, nodeB = base + w + 8;
    int g = lane >> 3, s = lane & 7;

    if (tid < 16) {
        int nn = base + tid;
        if (nn < n) g_cnt[nn] = 0;      // counters clean for next graph replay
    }
    if (blockIdx.x == 0 && tid == 0) g_ctr = 0;
    if (nodeA >= n) return;

    int iA = g_rowptr[nodeA], eA = g_rowend[nodeA];
    int iB = 0, eB = 0;
    if (nodeB < n) { iB = g_rowptr[nodeB]; eB = g_rowend[nodeB]; }

    const float4* Y = (const float4*)g_yb;
    float accA[8], accB[8];
    gather2(Y, iA, eA, iB, eB, g, s, accA, accB);

    if (g == 0) {
        const float4* Z = (const float4*)g_z2;
        #pragma unroll
        for (int half_ = 0; half_ < 2; ++half_) {
            int node = half_ ? nodeB : nodeA;
            float* acc = half_ ? accB : accA;
            if (node < n) {
                float inv = g_invdeg[node];
                float4 z0 = Z[node * 16 + s * 2];
                float4 z1 = Z[node * 16 + s * 2 + 1];
                float4 o0 = make_float4(acc[0]*inv + z0.x, acc[1]*inv + z0.y,
                                        acc[2]*inv + z0.z, acc[3]*inv + z0.w);
                float4 o1 = make_float4(acc[4]*inv + z1.x, acc[5]*inv + z1.y,
                                        acc[6]*inv + z1.z, acc[7]*inv + z1.w);
                *(float4*)&Og[node * 64 + s * 8]     = o0;
                *(float4*)&Og[node * 64 + s * 8 + 4] = o1;
            }
        }
    }
}

// ------------------------------------------------------------------- launch
extern "C" void kernel_launch(void* const* d_in, const int* in_sizes, int n_in,
                              void* d_out, int out_size) {
    const float* x   = (const float*)d_in[0];
    const int*   ei  = (const int*)d_in[1];
    const float* w1l = (const float*)d_in[2];
    const float* b1l = (const float*)d_in[3];
    const float* w1r = (const float*)d_in[4];
    const float* w2l = (const float*)d_in[5];
    const float* b2l = (const float*)d_in[6];
    const float* w2r = (const float*)d_in[7];
    float* out = (float*)d_out;

    int n = in_sizes[0] / F;
    int E = in_sizes[1] / 2;
    const int* src = ei;
    const int* dst = ei + E;

    int HB = (E + 1023) / 1024;          // hist blocks (4 edges/thread)
    int GB = (n + 63) / 64;              // gemm blocks

    k_histgemm<<<HB + GB, 256>>>(dst, E, HB, x, w1l, w1r, b1l, n);
    k_scan    <<<(n + 1023) / 1024, 1024>>>(n);
    k_scatter <<<(E / 4 + 255) / 256, 256>>>(src, dst, E);

    k_fused <<<GB, 256>>>(w2l, w2r, b2l, n);
    k_agg2  <<<(n + 15) / 16, 256>>>(out, n);
}

// round 12
// speedup vs baseline: 1.0498x; 1.0035x over previous
#include <cuda_runtime.h>
#include <cuda_fp16.h>
#include <cstdint>

// GraphSAGE 2-layer encoder.
//   y = h@Wl (fp16), z = h@Wr + b (fp32), out[i] = inv[i]*sum_{j in N(i)} y[j] + z[i]
// HMMA GEMMs. Gather kernels are split from MMA kernels so the gathers run
// register-lean at high occupancy (latency x concurrency bound).

#define NMAX 100000
#define EMAX 1600000
#define F 64
#define TS 72   // smem row stride in halves (144B, 16B-aligned rows)

__device__ __align__(16) __half g_ya[NMAX * F];
__device__ __align__(16) __half g_yb[NMAX * F];
__device__ __align__(16) __half g_h [NMAX * F];
__device__ __align__(16) float  g_z1[NMAX * F];
__device__ __align__(16) float  g_z2[NMAX * F];
__device__ float g_invdeg[NMAX];
__device__ int   g_cnt[NMAX];        // zero-init at load; re-zeroed by k_agg2
__device__ int   g_rowptr[NMAX];
__device__ int   g_rowend[NMAX];
__device__ int   g_pos[EMAX];
__device__ int   g_col[EMAX];
__device__ int   g_ctr;              // chunk-base counter (re-zeroed by k_agg2)

// ---------------------------------------------------------------- MMA bits
__device__ __forceinline__ unsigned smem_u32(const void* p) {
    return (unsigned)__cvta_generic_to_shared(p);
}
__device__ __forceinline__ void ldsm_x4(unsigned& a0, unsigned& a1,
                                        unsigned& a2, unsigned& a3, unsigned addr) {
    asm volatile("ldmatrix.sync.aligned.m8n8.x4.shared.b16 {%0,%1,%2,%3}, [%4];"
                 : "=r"(a0), "=r"(a1), "=r"(a2), "=r"(a3) : "r"(addr));
}
__device__ __forceinline__ void ldsm_x2t(unsigned& b0, unsigned& b1, unsigned addr) {
    asm volatile("ldmatrix.sync.aligned.m8n8.x2.trans.shared.b16 {%0,%1}, [%2];"
                 : "=r"(b0), "=r"(b1) : "r"(addr));
}
__device__ __forceinline__ void mma16816(float* d, unsigned a0, unsigned a1,
                                         unsigned a2, unsigned a3,
                                         unsigned b0, unsigned b1) {
    asm volatile("mma.sync.aligned.m16n8k16.row.col.f32.f16.f16.f32 "
                 "{%0,%1,%2,%3}, {%4,%5,%6,%7}, {%8,%9}, {%0,%1,%2,%3};"
                 : "+f"(d[0]), "+f"(d[1]), "+f"(d[2]), "+f"(d[3])
                 : "r"(a0), "r"(a1), "r"(a2), "r"(a3), "r"(b0), "r"(b1));
}

// Dual GEMM on a 64-row tile: Y = A@Wl (fp16 out), Z = A@Wr + b (fp32 out).
__device__ __forceinline__ void mma_dual(const __half* xs, const __half* wls,
                                         const __half* wrs, const float* bs,
                                         __half* Yg, float* Zg, int row0, int n,
                                         int tid) {
    int w = tid >> 5, l = tid & 31;
    int m0 = (w & 3) * 16;
    int nb = (w >> 2) * 32;

    float acc0[4][4], acc1[4][4];
    #pragma unroll
    for (int j = 0; j < 4; ++j)
        #pragma unroll
        for (int q = 0; q < 4; ++q) { acc0[j][q] = 0.f; acc1[j][q] = 0.f; }

    int ag = l >> 3, ar = l & 7;
    int arow = m0 + (ag & 1) * 8 + ar;
    int acol = (ag >> 1) * 8;
    int br   = (l & 7) + ((l >> 3) & 1) * 8;

    #pragma unroll
    for (int kc = 0; kc < 4; ++kc) {
        int k0 = kc * 16;
        unsigned a0, a1, a2, a3;
        ldsm_x4(a0, a1, a2, a3, smem_u32(&xs[arow * TS + k0 + acol]));
        #pragma unroll
        for (int j = 0; j < 4; ++j) {
            int n0 = nb + j * 8;
            unsigned b0, b1, c0, c1;
            ldsm_x2t(b0, b1, smem_u32(&wls[(k0 + br) * TS + n0]));
            mma16816(acc0[j], a0, a1, a2, a3, b0, b1);
            ldsm_x2t(c0, c1, smem_u32(&wrs[(k0 + br) * TS + n0]));
            mma16816(acc1[j], a0, a1, a2, a3, c0, c1);
        }
    }

    int tr = l >> 2, tc = (l & 3) * 2;
    #pragma unroll
    for (int j = 0; j < 4; ++j) {
        int gc = nb + j * 8 + tc;
        float bx = bs[gc], by = bs[gc + 1];
        #pragma unroll
        for (int h = 0; h < 2; ++h) {
            int gr = row0 + m0 + tr + h * 8;
            if (gr < n) {
                *(__half2*)&Yg[gr * 64 + gc] =
                    __floats2half2_rn(acc0[j][h * 2], acc0[j][h * 2 + 1]);
                *(float2*)&Zg[gr * 64 + gc] =
                    make_float2(acc1[j][h * 2] + bx, acc1[j][h * 2 + 1] + by);
            }
        }
    }
}

// accumulate 8 halves (one float4) into 8 fp32 accumulators
__device__ __forceinline__ void add8(float* acc, float4 v) {
    __half2* h = (__half2*)&v;
    #pragma unroll
    for (int k = 0; k < 4; ++k) {
        float2 f = __half22float2(h[k]);
        acc[2 * k]     += f.x;
        acc[2 * k + 1] += f.y;
    }
}

// Warp-cooperative gather: lane = (g = l>>3 edge subgroup, s = l&7 dim chunk).
// Each lane loads float4 (16B) of the y-row; 4 edges per warp-step; 16 edges
// in flight. Full row sum lands in acc[8] of all lanes after shfl reduce.
__device__ __forceinline__ void gather_row(const float4* __restrict__ Y,
                                           int i0, int e,
                                           int g, int s, float* acc) {
    #pragma unroll
    for (int d = 0; d < 8; ++d) acc[d] = 0.f;
    int i = i0 + g;
    for (; i + 12 < e; i += 16) {
        float4 v0 = Y[g_col[i]      * 8 + s];
        float4 v1 = Y[g_col[i + 4]  * 8 + s];
        float4 v2 = Y[g_col[i + 8]  * 8 + s];
        float4 v3 = Y[g_col[i + 12] * 8 + s];
        add8(acc, v0); add8(acc, v1); add8(acc, v2); add8(acc, v3);
    }
    for (; i < e; i += 4) {
        add8(acc, Y[g_col[i] * 8 + s]);
    }
    __syncwarp();
    #pragma unroll
    for (int d = 0; d < 8; ++d) {
        acc[d] += __shfl_xor_sync(0xffffffffu, acc[d], 8);
        acc[d] += __shfl_xor_sync(0xffffffffu, acc[d], 16);
    }
}

// ------------------------------ fused histogram (CSR pass 1) + layer-1 GEMM
__global__ __launch_bounds__(256) void k_histgemm(const int* __restrict__ dst, int E, int HB,
                                                  const float* __restrict__ X,
                                                  const float* __restrict__ Wl,
                                                  const float* __restrict__ Wr,
                                                  const float* __restrict__ B,
                                                  int n) {
    if (blockIdx.x < (unsigned)HB) {
        int t  = blockIdx.x * 256 + threadIdx.x;
        int e4 = t * 4;
        if (e4 >= E) return;
        if (((E & 3) == 0) && e4 + 3 < E) {
            int4 d4 = ((const int4*)dst)[t];
            g_pos[e4 + 0] = atomicAdd(&g_cnt[d4.x], 1);
            g_pos[e4 + 1] = atomicAdd(&g_cnt[d4.y], 1);
            g_pos[e4 + 2] = atomicAdd(&g_cnt[d4.z], 1);
            g_pos[e4 + 3] = atomicAdd(&g_cnt[d4.w], 1);
        } else {
            int lim = min(e4 + 4, E);
            for (int e = e4; e < lim; ++e)
                g_pos[e] = atomicAdd(&g_cnt[dst[e]], 1);
        }
        return;
    }

    __shared__ __half xs[64 * TS];
    __shared__ __half wls[64 * TS];
    __shared__ __half wrs[64 * TS];
    __shared__ float  bs[64];

    int tid  = threadIdx.x;
    int row0 = ((int)blockIdx.x - HB) * 64;

    for (int t = tid; t < 1024; t += 256) {
        int r = t >> 4, c4 = (t & 15) << 2;
        float4 wl = ((const float4*)Wl)[t];
        float4 wr = ((const float4*)Wr)[t];
        *(__half2*)&wls[r * TS + c4]     = __floats2half2_rn(wl.x, wl.y);
        *(__half2*)&wls[r * TS + c4 + 2] = __floats2half2_rn(wl.z, wl.w);
        *(__half2*)&wrs[r * TS + c4]     = __floats2half2_rn(wr.x, wr.y);
        *(__half2*)&wrs[r * TS + c4 + 2] = __floats2half2_rn(wr.z, wr.w);

        int g = row0 + r;
        float4 v = make_float4(0.f, 0.f, 0.f, 0.f);
        if (g < n) v = *(const float4*)&X[g * 64 + c4];
        *(__half2*)&xs[r * TS + c4]     = __floats2half2_rn(v.x, v.y);
        *(__half2*)&xs[r * TS + c4 + 2] = __floats2half2_rn(v.z, v.w);
    }
    if (tid < 64) bs[tid] = B[tid];
    __syncthreads();

    mma_dual(xs, wls, wrs, bs, g_ya, g_z1, row0, n, tid);
}

// single-pass CSR scan: local chunk scan + atomic global base
__global__ void k_scan(int n) {
    __shared__ int sh[1024];
    __shared__ int base_sh;
    int tid = threadIdx.x;
    int i = blockIdx.x * 1024 + tid;
    int v = (i < n) ? g_cnt[i] : 0;
    sh[tid] = v;
    __syncthreads();
    #pragma unroll
    for (int off = 1; off < 1024; off <<= 1) {
        int t = (tid >= off) ? sh[tid - off] : 0;
        __syncthreads();
        sh[tid] += t;
        __syncthreads();
    }
    if (tid == 1023) base_sh = atomicAdd(&g_ctr, sh[1023]);
    __syncthreads();
    if (i < n) {
        int base = base_sh;
        int incl = sh[tid];
        g_rowptr[i] = base + incl - v;
        g_rowend[i] = base + incl;
        g_invdeg[i] = 1.0f / (float)max(v, 1);
    }
}

// atomic-free scatter, 4 edges/thread
__global__ void k_scatter(const int* __restrict__ src, const int* __restrict__ dst, int E) {
    int t  = blockIdx.x * blockDim.x + threadIdx.x;
    int e4 = t * 4;
    if (e4 >= E) return;
    if (((E & 3) == 0) && e4 + 3 < E) {
        int4 d4 = ((const int4*)dst)[t];
        int4 p4 = ((const int4*)g_pos)[t];
        int4 s4 = ((const int4*)src)[t];
        g_col[g_rowptr[d4.x] + p4.x] = s4.x;
        g_col[g_rowptr[d4.y] + p4.y] = s4.y;
        g_col[g_rowptr[d4.z] + p4.z] = s4.z;
        g_col[g_rowptr[d4.w] + p4.w] = s4.w;
    } else {
        int lim = min(e4 + 4, E);
        for (int e = e4; e < lim; ++e)
            g_col[g_rowptr[dst[e]] + g_pos[e]] = src[e];
    }
}

// --------------------------- layer-1 aggregate (lean, high-occupancy)
// h[i] = relu(inv*sum ya[col] + z1) -> g_h (fp16)
__global__ __launch_bounds__(256, 6) void k_agg1(int n) {
    int tid  = threadIdx.x;
    int lane = tid & 31, w = tid >> 5;
    int node = blockIdx.x * 8 + w;
    int g = lane >> 3, s = lane & 7;
    if (node >= n) return;

    const float4* Y = (const float4*)g_ya;
    float acc[8];
    gather_row(Y, g_rowptr[node], g_rowend[node], g, s, acc);

    if (g == 0) {
        float inv = g_invdeg[node];
        const float4* Z = (const float4*)g_z1;
        float4 z0 = Z[node * 16 + s * 2];
        float4 z1 = Z[node * 16 + s * 2 + 1];
        __half2 hh[4];
        hh[0] = __floats2half2_rn(fmaxf(acc[0]*inv + z0.x, 0.f),
                                  fmaxf(acc[1]*inv + z0.y, 0.f));
        hh[1] = __floats2half2_rn(fmaxf(acc[2]*inv + z0.z, 0.f),
                                  fmaxf(acc[3]*inv + z0.w, 0.f));
        hh[2] = __floats2half2_rn(fmaxf(acc[4]*inv + z1.x, 0.f),
                                  fmaxf(acc[5]*inv + z1.y, 0.f));
        hh[3] = __floats2half2_rn(fmaxf(acc[6]*inv + z1.z, 0.f),
                                  fmaxf(acc[7]*inv + z1.w, 0.f));
        *(float4*)&g_h[node * 64 + s * 8] = *(float4*)hh;
    }
}

// --------------------------------------------- layer-2 dual GEMM (from g_h)
__global__ __launch_bounds__(256) void k_gemm2(const float* __restrict__ Wl,
                                               const float* __restrict__ Wr,
                                               const float* __restrict__ B,
                                               int n) {
    __shared__ __half xs[64 * TS];
    __shared__ __half wls[64 * TS];
    __shared__ __half wrs[64 * TS];
    __shared__ float  bs[64];

    int tid  = threadIdx.x;
    int row0 = blockIdx.x * 64;

    for (int t = tid; t < 1024; t += 256) {
        int r = t >> 4, c4 = (t & 15) << 2;
        float4 wl = ((const float4*)Wl)[t];
        float4 wr = ((const float4*)Wr)[t];
        *(__half2*)&wls[r * TS + c4]     = __floats2half2_rn(wl.x, wl.y);
        *(__half2*)&wls[r * TS + c4 + 2] = __floats2half2_rn(wl.z, wl.w);
        *(__half2*)&wrs[r * TS + c4]     = __floats2half2_rn(wr.x, wr.y);
        *(__half2*)&wrs[r * TS + c4 + 2] = __floats2half2_rn(wr.z, wr.w);
    }
    // h tile: 64 rows x 64 halves, already fp16
    for (int t = tid; t < 512; t += 256) {
        int r = t >> 3, c8 = (t & 7) * 8;
        int g = row0 + r;
        float4 v = make_float4(0.f, 0.f, 0.f, 0.f);
        if (g < n) v = *(const float4*)&g_h[g * 64 + c8];
        *(float4*)&xs[r * TS + c8] = v;
    }
    if (tid < 64) bs[tid] = B[tid];
    __syncthreads();

    mma_dual(xs, wls, wrs, bs, g_yb, g_z2, row0, n, tid);
}

// --------------------------------------------------------- final aggregate
__global__ __launch_bounds__(256, 6) void k_agg2(float* __restrict__ Og, int n) {
    int tid  = threadIdx.x;
    int lane = tid & 31, w = tid >> 5;
    int node = blockIdx.x * 8 + w;
    int g = lane >> 3, s = lane & 7;

    if (tid < 8) {
        int nn = blockIdx.x * 8 + tid;
        if (nn < n) g_cnt[nn] = 0;      // counters clean for next graph replay
    }
    if (blockIdx.x == 0 && tid == 0) g_ctr = 0;
    if (node >= n) return;

    const float4* Y = (const float4*)g_yb;
    float acc[8];
    gather_row(Y, g_rowptr[node], g_rowend[node], g, s, acc);

    if (g == 0) {
        float inv = g_invdeg[node];
        const float4* Z = (const float4*)g_z2;
        float4 z0 = Z[node * 16 + s * 2];
        float4 z1 = Z[node * 16 + s * 2 + 1];
        float4 o0 = make_float4(acc[0]*inv + z0.x, acc[1]*inv + z0.y,
                                acc[2]*inv + z0.z, acc[3]*inv + z0.w);
        float4 o1 = make_float4(acc[4]*inv + z1.x, acc[5]*inv + z1.y,
                                acc[6]*inv + z1.z, acc[7]*inv + z1.w);
        *(float4*)&Og[node * 64 + s * 8]     = o0;
        *(float4*)&Og[node * 64 + s * 8 + 4] = o1;
    }
}

// ------------------------------------------------------------------- launch
extern "C" void kernel_launch(void* const* d_in, const int* in_sizes, int n_in,
                              void* d_out, int out_size) {
    const float* x   = (const float*)d_in[0];
    const int*   ei  = (const int*)d_in[1];
    const float* w1l = (const float*)d_in[2];
    const float* b1l = (const float*)d_in[3];
    const float* w1r = (const float*)d_in[4];
    const float* w2l = (const float*)d_in[5];
    const float* b2l = (const float*)d_in[6];
    const float* w2r = (const float*)d_in[7];
    float* out = (float*)d_out;

    int n = in_sizes[0] / F;
    int E = in_sizes[1] / 2;
    const int* src = ei;
    const int* dst = ei + E;

    int HB = (E + 1023) / 1024;          // hist blocks (4 edges/thread)
    int GB = (n + 63) / 64;              // gemm blocks

    k_histgemm<<<HB + GB, 256>>>(dst, E, HB, x, w1l, w1r, b1l, n);
    k_scan    <<<(n + 1023) / 1024, 1024>>>(n);
    k_scatter <<<(E / 4 + 255) / 256, 256>>>(src, dst, E);

    k_agg1 <<<(n + 7) / 8, 256>>>(n);
    k_gemm2<<<GB, 256>>>(w2l, w2r, b2l, n);
    k_agg2 <<<(n + 7) / 8, 256>>>(out, n);
}

// round 14
// speedup vs baseline: 1.0867x; 1.0352x over previous
#include <cuda_runtime.h>
#include <cuda_fp16.h>
#include <cstdint>

// GraphSAGE 2-layer encoder.
//   y = h@Wl (fp16), z = h@Wr + b (fp32), out[i] = inv[i]*sum_{j in N(i)} y[j] + z[i]
// HMMA GEMMs; lean high-occupancy gather kernels. Edge lists are padded to a
// multiple of 16 with a dummy zero-row index so the gather has NO tail and a
// 5x leaner inner loop (fp16 pair-tree + single fp32 accumulate).

#define NMAX 100000
#define EMAX 1600000
#define EPAD (EMAX + 16 * NMAX)
#define F 64
#define TS 72   // smem row stride in halves (144B, 16B-aligned rows)

// +16 rows: row n (dummy) stays zero forever (BSS zero-init, never written)
__device__ __align__(16) __half g_ya[(NMAX + 16) * F];
__device__ __align__(16) __half g_yb[(NMAX + 16) * F];
__device__ __align__(16) __half g_h [NMAX * F];
__device__ __align__(16) float  g_z1[NMAX * F];
__device__ __align__(16) float  g_z2[NMAX * F];
__device__ float g_invdeg[NMAX];
__device__ int   g_cnt[NMAX];        // zero-init at load; re-zeroed by k_agg2
__device__ int   g_rowptr[NMAX];
__device__ int   g_rowend[NMAX];     // = rowptr + padded count (mult of 16)
__device__ int   g_pos[EMAX];
__device__ int   g_col[EPAD];
__device__ int   g_ctr;              // chunk-base counter (re-zeroed by k_agg2)

// ---------------------------------------------------------------- MMA bits
__device__ __forceinline__ unsigned smem_u32(const void* p) {
    return (unsigned)__cvta_generic_to_shared(p);
}
__device__ __forceinline__ void ldsm_x4(unsigned& a0, unsigned& a1,
                                        unsigned& a2, unsigned& a3, unsigned addr) {
    asm volatile("ldmatrix.sync.aligned.m8n8.x4.shared.b16 {%0,%1,%2,%3}, [%4];"
                 : "=r"(a0), "=r"(a1), "=r"(a2), "=r"(a3) : "r"(addr));
}
__device__ __forceinline__ void ldsm_x2t(unsigned& b0, unsigned& b1, unsigned addr) {
    asm volatile("ldmatrix.sync.aligned.m8n8.x2.trans.shared.b16 {%0,%1}, [%2];"
                 : "=r"(b0), "=r"(b1) : "r"(addr));
}
__device__ __forceinline__ void mma16816(float* d, unsigned a0, unsigned a1,
                                         unsigned a2, unsigned a3,
                                         unsigned b0, unsigned b1) {
    asm volatile("mma.sync.aligned.m16n8k16.row.col.f32.f16.f16.f32 "
                 "{%0,%1,%2,%3}, {%4,%5,%6,%7}, {%8,%9}, {%0,%1,%2,%3};"
                 : "+f"(d[0]), "+f"(d[1]), "+f"(d[2]), "+f"(d[3])
                 : "r"(a0), "r"(a1), "r"(a2), "r"(a3), "r"(b0), "r"(b1));
}

// Dual GEMM on a 64-row tile: Y = A@Wl (fp16 out), Z = A@Wr + b (fp32 out).
__device__ __forceinline__ void mma_dual(const __half* xs, const __half* wls,
                                         const __half* wrs, const float* bs,
                                         __half* Yg, float* Zg, int row0, int n,
                                         int tid) {
    int w = tid >> 5, l = tid & 31;
    int m0 = (w & 3) * 16;
    int nb = (w >> 2) * 32;

    float acc0[4][4], acc1[4][4];
    #pragma unroll
    for (int j = 0; j < 4; ++j)
        #pragma unroll
        for (int q = 0; q < 4; ++q) { acc0[j][q] = 0.f; acc1[j][q] = 0.f; }

    int ag = l >> 3, ar = l & 7;
    int arow = m0 + (ag & 1) * 8 + ar;
    int acol = (ag >> 1) * 8;
    int br   = (l & 7) + ((l >> 3) & 1) * 8;

    #pragma unroll
    for (int kc = 0; kc < 4; ++kc) {
        int k0 = kc * 16;
        unsigned a0, a1, a2, a3;
        ldsm_x4(a0, a1, a2, a3, smem_u32(&xs[arow * TS + k0 + acol]));
        #pragma unroll
        for (int j = 0; j < 4; ++j) {
            int n0 = nb + j * 8;
            unsigned b0, b1, c0, c1;
            ldsm_x2t(b0, b1, smem_u32(&wls[(k0 + br) * TS + n0]));
            mma16816(acc0[j], a0, a1, a2, a3, b0, b1);
            ldsm_x2t(c0, c1, smem_u32(&wrs[(k0 + br) * TS + n0]));
            mma16816(acc1[j], a0, a1, a2, a3, c0, c1);
        }
    }

    int tr = l >> 2, tc = (l & 3) * 2;
    #pragma unroll
    for (int j = 0; j < 4; ++j) {
        int gc = nb + j * 8 + tc;
        float bx = bs[gc], by = bs[gc + 1];
        #pragma unroll
        for (int h = 0; h < 2; ++h) {
            int gr = row0 + m0 + tr + h * 8;
            if (gr < n) {
                *(__half2*)&Yg[gr * 64 + gc] =
                    __floats2half2_rn(acc0[j][h * 2], acc0[j][h * 2 + 1]);
                *(float2*)&Zg[gr * 64 + gc] =
                    make_float2(acc1[j][h * 2] + bx, acc1[j][h * 2 + 1] + by);
            }
        }
    }
}

// Warp-cooperative gather over a PADDED edge range (length % 16 == 0).
// lane = (g = l>>3 edge subgroup, s = l&7 dim chunk); lane loads float4
// (8 halves) of the y-row; 4 edges/warp-step; 16 edges in flight; fp16
// pair-tree (12 HADD2) then one fp32 accumulate per 16 edges. No tail.
__device__ __forceinline__ void gather_row(const float4* __restrict__ Y,
                                           int i0, int e,
                                           int g, int s, float* acc) {
    #pragma unroll
    for (int d = 0; d < 8; ++d) acc[d] = 0.f;
    for (int i = i0 + g; i < e; i += 16) {
        float4 v0 = Y[g_col[i]      * 8 + s];
        float4 v1 = Y[g_col[i + 4]  * 8 + s];
        float4 v2 = Y[g_col[i + 8]  * 8 + s];
        float4 v3 = Y[g_col[i + 12] * 8 + s];
        __half2* h0 = (__half2*)&v0;
        __half2* h1 = (__half2*)&v1;
        __half2* h2 = (__half2*)&v2;
        __half2* h3 = (__half2*)&v3;
        #pragma unroll
        for (int k = 0; k < 4; ++k) {
            __half2 t = __hadd2(__hadd2(h0[k], h1[k]), __hadd2(h2[k], h3[k]));
            float2 f = __half22float2(t);
            acc[2 * k]     += f.x;
            acc[2 * k + 1] += f.y;
        }
    }
    __syncwarp();
    #pragma unroll
    for (int d = 0; d < 8; ++d) {
        acc[d] += __shfl_xor_sync(0xffffffffu, acc[d], 8);
        acc[d] += __shfl_xor_sync(0xffffffffu, acc[d], 16);
    }
}

// ------------------------------ fused histogram (CSR pass 1) + layer-1 GEMM
__global__ __launch_bounds__(256) void k_histgemm(const int* __restrict__ dst, int E, int HB,
                                                  const float* __restrict__ X,
                                                  const float* __restrict__ Wl,
                                                  const float* __restrict__ Wr,
                                                  const float* __restrict__ B,
                                                  int n) {
    if (blockIdx.x < (unsigned)HB) {
        int t  = blockIdx.x * 256 + threadIdx.x;
        int e4 = t * 4;
        if (e4 >= E) return;
        if (((E & 3) == 0) && e4 + 3 < E) {
            int4 d4 = ((const int4*)dst)[t];
            g_pos[e4 + 0] = atomicAdd(&g_cnt[d4.x], 1);
            g_pos[e4 + 1] = atomicAdd(&g_cnt[d4.y], 1);
            g_pos[e4 + 2] = atomicAdd(&g_cnt[d4.z], 1);
            g_pos[e4 + 3] = atomicAdd(&g_cnt[d4.w], 1);
        } else {
            int lim = min(e4 + 4, E);
            for (int e = e4; e < lim; ++e)
                g_pos[e] = atomicAdd(&g_cnt[dst[e]], 1);
        }
        return;
    }

    __shared__ __half xs[64 * TS];
    __shared__ __half wls[64 * TS];
    __shared__ __half wrs[64 * TS];
    __shared__ float  bs[64];

    int tid  = threadIdx.x;
    int row0 = ((int)blockIdx.x - HB) * 64;

    for (int t = tid; t < 1024; t += 256) {
        int r = t >> 4, c4 = (t & 15) << 2;
        float4 wl = ((const float4*)Wl)[t];
        float4 wr = ((const float4*)Wr)[t];
        *(__half2*)&wls[r * TS + c4]     = __floats2half2_rn(wl.x, wl.y);
        *(__half2*)&wls[r * TS + c4 + 2] = __floats2half2_rn(wl.z, wl.w);
        *(__half2*)&wrs[r * TS + c4]     = __floats2half2_rn(wr.x, wr.y);
        *(__half2*)&wrs[r * TS + c4 + 2] = __floats2half2_rn(wr.z, wr.w);

        int g = row0 + r;
        float4 v = make_float4(0.f, 0.f, 0.f, 0.f);
        if (g < n) v = *(const float4*)&X[g * 64 + c4];
        *(__half2*)&xs[r * TS + c4]     = __floats2half2_rn(v.x, v.y);
        *(__half2*)&xs[r * TS + c4 + 2] = __floats2half2_rn(v.z, v.w);
    }
    if (tid < 64) bs[tid] = B[tid];
    __syncthreads();

    mma_dual(xs, wls, wrs, bs, g_ya, g_z1, row0, n, tid);
}

// single-pass CSR scan over PADDED counts; fills padding with dummy index n.
__global__ void k_scan(int n) {
    __shared__ int sh[1024];
    __shared__ int base_sh;
    int tid = threadIdx.x;
    int i = blockIdx.x * 1024 + tid;
    int v  = (i < n) ? g_cnt[i] : 0;
    int pc = (v + 15) & ~15;             // padded count (multiple of 16)
    sh[tid] = pc;
    __syncthreads();
    #pragma unroll
    for (int off = 1; off < 1024; off <<= 1) {
        int t = (tid >= off) ? sh[tid - off] : 0;
        __syncthreads();
        sh[tid] += t;
        __syncthreads();
    }
    if (tid == 1023) base_sh = atomicAdd(&g_ctr, sh[1023]);
    __syncthreads();
    if (i < n) {
        int rp = base_sh + sh[tid] - pc;
        g_rowptr[i] = rp;
        g_rowend[i] = rp + pc;
        g_invdeg[i] = 1.0f / (float)max(v, 1);
        for (int p = v; p < pc; ++p) g_col[rp + p] = n;   // dummy zero row
    }
}

// atomic-free scatter, 4 edges/thread
__global__ void k_scatter(const int* __restrict__ src, const int* __restrict__ dst, int E) {
    int t  = blockIdx.x * blockDim.x + threadIdx.x;
    int e4 = t * 4;
    if (e4 >= E) return;
    if (((E & 3) == 0) && e4 + 3 < E) {
        int4 d4 = ((const int4*)dst)[t];
        int4 p4 = ((const int4*)g_pos)[t];
        int4 s4 = ((const int4*)src)[t];
        g_col[g_rowptr[d4.x] + p4.x] = s4.x;
        g_col[g_rowptr[d4.y] + p4.y] = s4.y;
        g_col[g_rowptr[d4.z] + p4.z] = s4.z;
        g_col[g_rowptr[d4.w] + p4.w] = s4.w;
    } else {
        int lim = min(e4 + 4, E);
        for (int e = e4; e < lim; ++e)
            g_col[g_rowptr[dst[e]] + g_pos[e]] = src[e];
    }
}

// --------------------------- layer-1 aggregate (lean, high-occupancy)
// h[i] = relu(inv*sum ya[col] + z1) -> g_h (fp16)
__global__ __launch_bounds__(256, 6) void k_agg1(int n) {
    int tid  = threadIdx.x;
    int lane = tid & 31, w = tid >> 5;
    int node = blockIdx.x * 8 + w;
    int g = lane >> 3, s = lane & 7;
    if (node >= n) return;

    const float4* Y = (const float4*)g_ya;
    float acc[8];
    gather_row(Y, g_rowptr[node], g_rowend[node], g, s, acc);

    if (g == 0) {
        float inv = g_invdeg[node];
        const float4* Z = (const float4*)g_z1;
        float4 z0 = Z[node * 16 + s * 2];
        float4 z1 = Z[node * 16 + s * 2 + 1];
        __half2 hh[4];
        hh[0] = __floats2half2_rn(fmaxf(acc[0]*inv + z0.x, 0.f),
                                  fmaxf(acc[1]*inv + z0.y, 0.f));
        hh[1] = __floats2half2_rn(fmaxf(acc[2]*inv + z0.z, 0.f),
                                  fmaxf(acc[3]*inv + z0.w, 0.f));
        hh[2] = __floats2half2_rn(fmaxf(acc[4]*inv + z1.x, 0.f),
                                  fmaxf(acc[5]*inv + z1.y, 0.f));
        hh[3] = __floats2half2_rn(fmaxf(acc[6]*inv + z1.z, 0.f),
                                  fmaxf(acc[7]*inv + z1.w, 0.f));
        *(float4*)&g_h[node * 64 + s * 8] = *(float4*)hh;
    }
}

// --------------------------------------------- layer-2 dual GEMM (from g_h)
__global__ __launch_bounds__(256) void k_gemm2(const float* __restrict__ Wl,
                                               const float* __restrict__ Wr,
                                               const float* __restrict__ B,
                                               int n) {
    __shared__ __half xs[64 * TS];
    __shared__ __half wls[64 * TS];
    __shared__ __half wrs[64 * TS];
    __shared__ float  bs[64];

    int tid  = threadIdx.x;
    int row0 = blockIdx.x * 64;

    for (int t = tid; t < 1024; t += 256) {
        int r = t >> 4, c4 = (t & 15) << 2;
        float4 wl = ((const float4*)Wl)[t];
        float4 wr = ((const float4*)Wr)[t];
        *(__half2*)&wls[r * TS + c4]     = __floats2half2_rn(wl.x, wl.y);
        *(__half2*)&wls[r * TS + c4 + 2] = __floats2half2_rn(wl.z, wl.w);
        *(__half2*)&wrs[r * TS + c4]     = __floats2half2_rn(wr.x, wr.y);
        *(__half2*)&wrs[r * TS + c4 + 2] = __floats2half2_rn(wr.z, wr.w);
    }
    // h tile: 64 rows x 64 halves, already fp16
    for (int t = tid; t < 512; t += 256) {
        int r = t >> 3, c8 = (t & 7) * 8;
        int g = row0 + r;
        float4 v = make_float4(0.f, 0.f, 0.f, 0.f);
        if (g < n) v = *(const float4*)&g_h[g * 64 + c8];
        *(float4*)&xs[r * TS + c8] = v;
    }
    if (tid < 64) bs[tid] = B[tid];
    __syncthreads();

    mma_dual(xs, wls, wrs, bs, g_yb, g_z2, row0, n, tid);
}

// --------------------------------------------------------- final aggregate
__global__ __launch_bounds__(256, 6) void k_agg2(float* __restrict__ Og, int n) {
    int tid  = threadIdx.x;
    int lane = tid & 31, w = tid >> 5;
    int node = blockIdx.x * 8 + w;
    int g = lane >> 3, s = lane & 7;

    if (tid < 8) {
        int nn = blockIdx.x * 8 + tid;
        if (nn < n) g_cnt[nn] = 0;      // counters clean for next graph replay
    }
    if (blockIdx.x == 0 && tid == 0) g_ctr = 0;
    if (node >= n) return;

    const float4* Y = (const float4*)g_yb;
    float acc[8];
    gather_row(Y, g_rowptr[node], g_rowend[node], g, s, acc);

    if (g == 0) {
        float inv = g_invdeg[node];
        const float4* Z = (const float4*)g_z2;
        float4 z0 = Z[node * 16 + s * 2];
        float4 z1 = Z[node * 16 + s * 2 + 1];
        float4 o0 = make_float4(acc[0]*inv + z0.x, acc[1]*inv + z0.y,
                                acc[2]*inv + z0.z, acc[3]*inv + z0.w);
        float4 o1 = make_float4(acc[4]*inv + z1.x, acc[5]*inv + z1.y,
                                acc[6]*inv + z1.z, acc[7]*inv + z1.w);
        *(float4*)&Og[node * 64 + s * 8]     = o0;
        *(float4*)&Og[node * 64 + s * 8 + 4] = o1;
    }
}

// ------------------------------------------------------------------- launch
extern "C" void kernel_launch(void* const* d_in, const int* in_sizes, int n_in,
                              void* d_out, int out_size) {
    const float* x   = (const float*)d_in[0];
    const int*   ei  = (const int*)d_in[1];
    const float* w1l = (const float*)d_in[2];
    const float* b1l = (const float*)d_in[3];
    const float* w1r = (const float*)d_in[4];
    const float* w2l = (const float*)d_in[5];
    const float* b2l = (const float*)d_in[6];
    const float* w2r = (const float*)d_in[7];
    float* out = (float*)d_out;

    int n = in_sizes[0] / F;
    int E = in_sizes[1] / 2;
    const int* src = ei;
    const int* dst = ei + E;

    int HB = (E + 1023) / 1024;          // hist blocks (4 edges/thread)
    int GB = (n + 63) / 64;              // gemm blocks

    k_histgemm<<<HB + GB, 256>>>(dst, E, HB, x, w1l, w1r, b1l, n);
    k_scan    <<<(n + 1023) / 1024, 1024>>>(n);
    k_scatter <<<(E / 4 + 255) / 256, 256>>>(src, dst, E);

    k_agg1 <<<(n + 7) / 8, 256>>>(n);
    k_gemm2<<<GB, 256>>>(w2l, w2r, b2l, n);
    k_agg2 <<<(n + 7) / 8, 256>>>(out, n);
}

// round 15
// speedup vs baseline: 1.1552x; 1.0631x over previous
#include <cuda_runtime.h>
#include <cuda_fp16.h>
#include <cstdint>

// GraphSAGE 2-layer encoder, gather-before-GEMM form (linearity):
//   m[i] = inv[i] * sum_{j in N(i)} h[j]          (fp16 gather)
//   out  = [m | h] @ [Wl; Wr] + b                 (single K=128 HMMA GEMM)
// Edge lists padded to multiples of 16 (dummy zero row) -> tail-free gather.

#define NMAX 100000
#define EMAX 1600000
#define EPAD (EMAX + 16 * NMAX)
#define F 64
#define TSB 72    // B-tile row stride (halves)
#define TSA 136   // A-tile row stride (halves), 272B -> conflict-free ldsm

// +16 rows: row n (dummy) stays zero forever (BSS zero-init, never written)
__device__ __align__(16) __half g_xh[(NMAX + 16) * F];  // fp16 copy of x / layer input
__device__ __align__(16) __half g_h [(NMAX + 16) * F];  // layer-1 output
__device__ __align__(16) __half g_m [NMAX * F];         // aggregated means (reused)
__device__ float g_invdeg[NMAX];
__device__ int   g_cnt[NMAX];        // zero-init at load; re-zeroed by last kernel
__device__ int   g_rowptr[NMAX];
__device__ int   g_rowend[NMAX];     // rowptr + padded count (mult of 16)
__device__ int   g_pos[EMAX];
__device__ int   g_col[EPAD];
__device__ int   g_ctr;              // chunk-base counter (re-zeroed by last kernel)

// ---------------------------------------------------------------- MMA bits
__device__ __forceinline__ unsigned smem_u32(const void* p) {
    return (unsigned)__cvta_generic_to_shared(p);
}
__device__ __forceinline__ void ldsm_x4(unsigned& a0, unsigned& a1,
                                        unsigned& a2, unsigned& a3, unsigned addr) {
    asm volatile("ldmatrix.sync.aligned.m8n8.x4.shared.b16 {%0,%1,%2,%3}, [%4];"
                 : "=r"(a0), "=r"(a1), "=r"(a2), "=r"(a3) : "r"(addr));
}
__device__ __forceinline__ void ldsm_x2t(unsigned& b0, unsigned& b1, unsigned addr) {
    asm volatile("ldmatrix.sync.aligned.m8n8.x2.trans.shared.b16 {%0,%1}, [%2];"
                 : "=r"(b0), "=r"(b1) : "r"(addr));
}
__device__ __forceinline__ void mma16816(float* d, unsigned a0, unsigned a1,
                                         unsigned a2, unsigned a3,
                                         unsigned b0, unsigned b1) {
    asm volatile("mma.sync.aligned.m16n8k16.row.col.f32.f16.f16.f32 "
                 "{%0,%1,%2,%3}, {%4,%5,%6,%7}, {%8,%9}, {%0,%1,%2,%3};"
                 : "+f"(d[0]), "+f"(d[1]), "+f"(d[2]), "+f"(d[3])
                 : "r"(a0), "r"(a1), "r"(a2), "r"(a3), "r"(b0), "r"(b1));
}

// Warp-cooperative gather over a PADDED edge range (length % 16 == 0).
// lane = (g = l>>3 edge subgroup, s = l&7 dim chunk); fp16 pair-tree then
// one fp32 accumulate per 16 edges; full row sum on all lanes after shfl.
__device__ __forceinline__ void gather_row(const float4* __restrict__ Y,
                                           int i0, int e,
                                           int g, int s, float* acc) {
    #pragma unroll
    for (int d = 0; d < 8; ++d) acc[d] = 0.f;
    for (int i = i0 + g; i < e; i += 16) {
        float4 v0 = Y[g_col[i]      * 8 + s];
        float4 v1 = Y[g_col[i + 4]  * 8 + s];
        float4 v2 = Y[g_col[i + 8]  * 8 + s];
        float4 v3 = Y[g_col[i + 12] * 8 + s];
        __half2* h0 = (__half2*)&v0;
        __half2* h1 = (__half2*)&v1;
        __half2* h2 = (__half2*)&v2;
        __half2* h3 = (__half2*)&v3;
        #pragma unroll
        for (int k = 0; k < 4; ++k) {
            __half2 t = __hadd2(__hadd2(h0[k], h1[k]), __hadd2(h2[k], h3[k]));
            float2 f = __half22float2(t);
            acc[2 * k]     += f.x;
            acc[2 * k + 1] += f.y;
        }
    }
    __syncwarp();
    #pragma unroll
    for (int d = 0; d < 8; ++d) {
        acc[d] += __shfl_xor_sync(0xffffffffu, acc[d], 8);
        acc[d] += __shfl_xor_sync(0xffffffffu, acc[d], 16);
    }
}

// ------------------ fused histogram (CSR pass 1) + x -> fp16 conversion
__global__ __launch_bounds__(256) void k_histprep(const int* __restrict__ dst, int E, int HB,
                                                  const float* __restrict__ X, int n) {
    if (blockIdx.x < (unsigned)HB) {
        int t  = blockIdx.x * 256 + threadIdx.x;
        int e4 = t * 4;
        if (e4 >= E) return;
        if (((E & 3) == 0) && e4 + 3 < E) {
            int4 d4 = ((const int4*)dst)[t];
            g_pos[e4 + 0] = atomicAdd(&g_cnt[d4.x], 1);
            g_pos[e4 + 1] = atomicAdd(&g_cnt[d4.y], 1);
            g_pos[e4 + 2] = atomicAdd(&g_cnt[d4.z], 1);
            g_pos[e4 + 3] = atomicAdd(&g_cnt[d4.w], 1);
        } else {
            int lim = min(e4 + 4, E);
            for (int e = e4; e < lim; ++e)
                g_pos[e] = atomicAdd(&g_cnt[dst[e]], 1);
        }
        return;
    }
    // convert 8 floats -> 8 halves per thread
    int idx  = ((int)blockIdx.x - HB) * 256 + threadIdx.x;
    int base = idx * 8;
    if (base < n * 64) {
        float4 a = *(const float4*)&X[base];
        float4 b = *(const float4*)&X[base + 4];
        __half2 hh[4];
        hh[0] = __floats2half2_rn(a.x, a.y);
        hh[1] = __floats2half2_rn(a.z, a.w);
        hh[2] = __floats2half2_rn(b.x, b.y);
        hh[3] = __floats2half2_rn(b.z, b.w);
        *(float4*)&g_xh[base] = *(float4*)hh;
    }
}

// single-pass CSR scan over PADDED counts; fills padding with dummy index n.
__global__ void k_scan(int n) {
    __shared__ int sh[1024];
    __shared__ int base_sh;
    int tid = threadIdx.x;
    int i = blockIdx.x * 1024 + tid;
    int v  = (i < n) ? g_cnt[i] : 0;
    int pc = (v + 15) & ~15;             // padded count (multiple of 16)
    sh[tid] = pc;
    __syncthreads();
    #pragma unroll
    for (int off = 1; off < 1024; off <<= 1) {
        int t = (tid >= off) ? sh[tid - off] : 0;
        __syncthreads();
        sh[tid] += t;
        __syncthreads();
    }
    if (tid == 1023) base_sh = atomicAdd(&g_ctr, sh[1023]);
    __syncthreads();
    if (i < n) {
        int rp = base_sh + sh[tid] - pc;
        g_rowptr[i] = rp;
        g_rowend[i] = rp + pc;
        g_invdeg[i] = 1.0f / (float)max(v, 1);
        for (int p = v; p < pc; ++p) g_col[rp + p] = n;   // dummy zero row
    }
}

// atomic-free scatter, 4 edges/thread
__global__ void k_scatter(const int* __restrict__ src, const int* __restrict__ dst, int E) {
    int t  = blockIdx.x * blockDim.x + threadIdx.x;
    int e4 = t * 4;
    if (e4 >= E) return;
    if (((E & 3) == 0) && e4 + 3 < E) {
        int4 d4 = ((const int4*)dst)[t];
        int4 p4 = ((const int4*)g_pos)[t];
        int4 s4 = ((const int4*)src)[t];
        g_col[g_rowptr[d4.x] + p4.x] = s4.x;
        g_col[g_rowptr[d4.y] + p4.y] = s4.y;
        g_col[g_rowptr[d4.z] + p4.z] = s4.z;
        g_col[g_rowptr[d4.w] + p4.w] = s4.w;
    } else {
        int lim = min(e4 + 4, E);
        for (int e = e4; e < lim; ++e)
            g_col[g_rowptr[dst[e]] + g_pos[e]] = src[e];
    }
}

// --------------------------- aggregate: m[i] = inv * sum rows of (layer? h : xh)
__global__ __launch_bounds__(256, 7) void k_agg(int layer, int n) {
    int tid  = threadIdx.x;
    int lane = tid & 31, w = tid >> 5;
    int node = blockIdx.x * 8 + w;
    int g = lane >> 3, s = lane & 7;
    if (node >= n) return;

    const float4* Y = (const float4*)(layer ? g_h : g_xh);
    float acc[8];
    gather_row(Y, g_rowptr[node], g_rowend[node], g, s, acc);

    if (g == 0) {
        float inv = g_invdeg[node];
        __half2 hh[4];
        hh[0] = __floats2half2_rn(acc[0] * inv, acc[1] * inv);
        hh[1] = __floats2half2_rn(acc[2] * inv, acc[3] * inv);
        hh[2] = __floats2half2_rn(acc[4] * inv, acc[5] * inv);
        hh[3] = __floats2half2_rn(acc[6] * inv, acc[7] * inv);
        *(float4*)&g_m[node * 64 + s * 8] = *(float4*)hh;
    }
}

// ------------- concat GEMM: out = [m | Yin] @ [Wl; Wr] + b  (K = 128)
// layer 0: Yin = xh, out -> g_h (relu, fp16). layer 1: Yin = h, out -> Og (fp32).
__global__ __launch_bounds__(256) void k_gemm(const float* __restrict__ Wl,
                                              const float* __restrict__ Wr,
                                              const float* __restrict__ B,
                                              float* __restrict__ Og,
                                              int layer, int n) {
    __shared__ __half xs[64 * TSA];
    __shared__ __half ws[128 * TSB];
    __shared__ float  bs[64];

    int tid  = threadIdx.x;
    int row0 = blockIdx.x * 64;

    // B tile: rows 0-63 = Wl, rows 64-127 = Wr  (row-major [64,64] each)
    for (int t = tid; t < 2048; t += 256) {
        int r = t >> 4, c4 = (t & 15) << 2;
        const float* Wsrc = (r < 64) ? &Wl[r * 64 + c4] : &Wr[(r - 64) * 64 + c4];
        float4 v = *(const float4*)Wsrc;
        *(__half2*)&ws[r * TSB + c4]     = __floats2half2_rn(v.x, v.y);
        *(__half2*)&ws[r * TSB + c4 + 2] = __floats2half2_rn(v.z, v.w);
    }
    // A tile: cols 0-63 = m, cols 64-127 = Yin (both fp16 already)
    const __half* Yin = layer ? g_h : g_xh;
    for (int t = tid; t < 1024; t += 256) {
        int r = t >> 4, cc = t & 15;
        int gr = row0 + r;
        float4 v = make_float4(0.f, 0.f, 0.f, 0.f);
        if (gr < n) {
            v = (cc < 8) ? *(const float4*)&g_m[gr * 64 + cc * 8]
                         : *(const float4*)&Yin[gr * 64 + (cc - 8) * 8];
        }
        *(float4*)&xs[r * TSA + cc * 8] = v;
    }
    if (tid < 64) bs[tid] = B[tid];
    // cleanup (last kernel in chain when layer==1)
    if (layer && tid < 64) {
        int nn = row0 + tid;
        if (nn < n) g_cnt[nn] = 0;
    }
    if (layer && blockIdx.x == 0 && tid == 0) g_ctr = 0;
    __syncthreads();

    int w = tid >> 5, l = tid & 31;
    int m0 = (w & 3) * 16;
    int nb = (w >> 2) * 32;

    float acc[4][4];
    #pragma unroll
    for (int j = 0; j < 4; ++j)
        #pragma unroll
        for (int q = 0; q < 4; ++q) acc[j][q] = 0.f;

    int ag = l >> 3, ar = l & 7;
    int arow = m0 + (ag & 1) * 8 + ar;
    int acol = (ag >> 1) * 8;
    int br   = (l & 7) + ((l >> 3) & 1) * 8;

    #pragma unroll
    for (int kc = 0; kc < 8; ++kc) {
        int k0 = kc * 16;
        unsigned a0, a1, a2, a3;
        ldsm_x4(a0, a1, a2, a3, smem_u32(&xs[arow * TSA + k0 + acol]));
        #pragma unroll
        for (int j = 0; j < 4; ++j) {
            unsigned b0, b1;
            ldsm_x2t(b0, b1, smem_u32(&ws[(k0 + br) * TSB + nb + j * 8]));
            mma16816(acc[j], a0, a1, a2, a3, b0, b1);
        }
    }

    int tr = l >> 2, tc = (l & 3) * 2;
    #pragma unroll
    for (int j = 0; j < 4; ++j) {
        int gc = nb + j * 8 + tc;
        float bx = bs[gc], by = bs[gc + 1];
        #pragma unroll
        for (int h = 0; h < 2; ++h) {
            int gr = row0 + m0 + tr + h * 8;
            if (gr < n) {
                float vx = acc[j][h * 2]     + bx;
                float vy = acc[j][h * 2 + 1] + by;
                if (layer == 0) {
                    *(__half2*)&g_h[gr * 64 + gc] =
                        __floats2half2_rn(fmaxf(vx, 0.f), fmaxf(vy, 0.f));
                } else {
                    *(float2*)&Og[gr * 64 + gc] = make_float2(vx, vy);
                }
            }
        }
    }
}

// ------------------------------------------------------------------- launch
extern "C" void kernel_launch(void* const* d_in, const int* in_sizes, int n_in,
                              void* d_out, int out_size) {
    const float* x   = (const float*)d_in[0];
    const int*   ei  = (const int*)d_in[1];
    const float* w1l = (const float*)d_in[2];
    const float* b1l = (const float*)d_in[3];
    const float* w1r = (const float*)d_in[4];
    const float* w2l = (const float*)d_in[5];
    const float* b2l = (const float*)d_in[6];
    const float* w2r = (const float*)d_in[7];
    float* out = (float*)d_out;

    int n = in_sizes[0] / F;
    int E = in_sizes[1] / 2;
    const int* src = ei;
    const int* dst = ei + E;

    int HB = (E + 1023) / 1024;              // hist blocks (4 edges/thread)
    int CB = (n * 8 + 255) / 256;            // convert blocks (8 floats/thread)
    int GB = (n + 63) / 64;                  // gemm blocks

    k_histprep<<<HB + CB, 256>>>(dst, E, HB, x, n);
    k_scan    <<<(n + 1023) / 1024, 1024>>>(n);
    k_scatter <<<(E / 4 + 255) / 256, 256>>>(src, dst, E);

    k_agg <<<(n + 7) / 8, 256>>>(0, n);                      // m = agg(xh)
    k_gemm<<<GB, 256>>>(w1l, w1r, b1l, nullptr, 0, n);       // h = relu([m|xh]@W1+b1)
    k_agg <<<(n + 7) / 8, 256>>>(1, n);                      // m = agg(h)
    k_gemm<<<GB, 256>>>(w2l, w2r, b2l, out, 1, n);           // out = [m|h]@W2+b2
}

// round 16
// speedup vs baseline: 1.1686x; 1.0116x over previous
#include <cuda_runtime.h>
#include <cuda_fp16.h>
#include <cstdint>

// GraphSAGE 2-layer encoder, gather-before-GEMM form (linearity):
//   m[i] = sum_{j in N(i)} h[j]                   (fp16 gather, raw sums)
//   out  = [inv*m | h] @ [Wl; Wr] + b             (single K=128 HMMA GEMM;
//                                                  inv folded into A-tile load)
// Edge lists padded to multiples of 16 (dummy zero row) -> tail-free gather.

#define NMAX 100000
#define EMAX 1600000
#define EPAD (EMAX + 16 * NMAX)
#define F 64
#define TSB 72    // B-tile row stride (halves)
#define TSA 136   // A-tile row stride (halves), 272B -> conflict-free ldsm

// +16 rows: row n (dummy) stays zero forever (BSS zero-init, never written)
__device__ __align__(16) __half g_xh[(NMAX + 16) * F];  // fp16 copy of x / layer input
__device__ __align__(16) __half g_h [(NMAX + 16) * F];  // layer-1 output
__device__ __align__(16) __half g_m [NMAX * F];         // aggregated sums (reused)
__device__ float g_invdeg[NMAX];
__device__ int   g_cnt[NMAX];        // zero-init at load; re-zeroed by last kernel
__device__ int   g_rowptr[NMAX];
__device__ int   g_rowend[NMAX];     // rowptr + padded count (mult of 16)
__device__ int   g_pos[EMAX];
__device__ int   g_col[EPAD];
__device__ int   g_ctr;              // chunk-base counter (re-zeroed by last kernel)

// ---------------------------------------------------------------- MMA bits
__device__ __forceinline__ unsigned smem_u32(const void* p) {
    return (unsigned)__cvta_generic_to_shared(p);
}
__device__ __forceinline__ void ldsm_x4(unsigned& a0, unsigned& a1,
                                        unsigned& a2, unsigned& a3, unsigned addr) {
    asm volatile("ldmatrix.sync.aligned.m8n8.x4.shared.b16 {%0,%1,%2,%3}, [%4];"
                 : "=r"(a0), "=r"(a1), "=r"(a2), "=r"(a3) : "r"(addr));
}
__device__ __forceinline__ void ldsm_x2t(unsigned& b0, unsigned& b1, unsigned addr) {
    asm volatile("ldmatrix.sync.aligned.m8n8.x2.trans.shared.b16 {%0,%1}, [%2];"
                 : "=r"(b0), "=r"(b1) : "r"(addr));
}
__device__ __forceinline__ void mma16816(float* d, unsigned a0, unsigned a1,
                                         unsigned a2, unsigned a3,
                                         unsigned b0, unsigned b1) {
    asm volatile("mma.sync.aligned.m16n8k16.row.col.f32.f16.f16.f32 "
                 "{%0,%1,%2,%3}, {%4,%5,%6,%7}, {%8,%9}, {%0,%1,%2,%3};"
                 : "+f"(d[0]), "+f"(d[1]), "+f"(d[2]), "+f"(d[3])
                 : "r"(a0), "r"(a1), "r"(a2), "r"(a3), "r"(b0), "r"(b1));
}

// Warp-cooperative gather over a PADDED edge range (length % 16 == 0).
// lane = (g = l>>3 edge subgroup, s = l&7 dim chunk); fp16 pair-tree then
// one fp32 accumulate per 16 edges; full row sum on all lanes after shfl.
__device__ __forceinline__ void gather_row(const float4* __restrict__ Y,
                                           int i0, int e,
                                           int g, int s, float* acc) {
    #pragma unroll
    for (int d = 0; d < 8; ++d) acc[d] = 0.f;
    for (int i = i0 + g; i < e; i += 16) {
        float4 v0 = Y[g_col[i]      * 8 + s];
        float4 v1 = Y[g_col[i + 4]  * 8 + s];
        float4 v2 = Y[g_col[i + 8]  * 8 + s];
        float4 v3 = Y[g_col[i + 12] * 8 + s];
        __half2* h0 = (__half2*)&v0;
        __half2* h1 = (__half2*)&v1;
        __half2* h2 = (__half2*)&v2;
        __half2* h3 = (__half2*)&v3;
        #pragma unroll
        for (int k = 0; k < 4; ++k) {
            __half2 t = __hadd2(__hadd2(h0[k], h1[k]), __hadd2(h2[k], h3[k]));
            float2 f = __half22float2(t);
            acc[2 * k]     += f.x;
            acc[2 * k + 1] += f.y;
        }
    }
    __syncwarp();
    #pragma unroll
    for (int d = 0; d < 8; ++d) {
        acc[d] += __shfl_xor_sync(0xffffffffu, acc[d], 8);
        acc[d] += __shfl_xor_sync(0xffffffffu, acc[d], 16);
    }
}

// ------------------ fused histogram (CSR pass 1) + x -> fp16 conversion
__global__ __launch_bounds__(256) void k_histprep(const int* __restrict__ dst, int E, int HB,
                                                  const float* __restrict__ X, int n) {
    if (blockIdx.x < (unsigned)HB) {
        int t  = blockIdx.x * 256 + threadIdx.x;
        int e4 = t * 4;
        if (e4 >= E) return;
        if (((E & 3) == 0) && e4 + 3 < E) {
            int4 d4 = ((const int4*)dst)[t];
            g_pos[e4 + 0] = atomicAdd(&g_cnt[d4.x], 1);
            g_pos[e4 + 1] = atomicAdd(&g_cnt[d4.y], 1);
            g_pos[e4 + 2] = atomicAdd(&g_cnt[d4.z], 1);
            g_pos[e4 + 3] = atomicAdd(&g_cnt[d4.w], 1);
        } else {
            int lim = min(e4 + 4, E);
            for (int e = e4; e < lim; ++e)
                g_pos[e] = atomicAdd(&g_cnt[dst[e]], 1);
        }
        return;
    }
    // convert 8 floats -> 8 halves per thread
    int idx  = ((int)blockIdx.x - HB) * 256 + threadIdx.x;
    int base = idx * 8;
    if (base < n * 64) {
        float4 a = *(const float4*)&X[base];
        float4 b = *(const float4*)&X[base + 4];
        __half2 hh[4];
        hh[0] = __floats2half2_rn(a.x, a.y);
        hh[1] = __floats2half2_rn(a.z, a.w);
        hh[2] = __floats2half2_rn(b.x, b.y);
        hh[3] = __floats2half2_rn(b.z, b.w);
        *(float4*)&g_xh[base] = *(float4*)hh;
    }
}

// single-pass CSR scan over PADDED counts; fills padding with dummy index n.
__global__ void k_scan(int n) {
    __shared__ int sh[1024];
    __shared__ int base_sh;
    int tid = threadIdx.x;
    int i = blockIdx.x * 1024 + tid;
    int v  = (i < n) ? g_cnt[i] : 0;
    int pc = (v + 15) & ~15;             // padded count (multiple of 16)
    sh[tid] = pc;
    __syncthreads();
    #pragma unroll
    for (int off = 1; off < 1024; off <<= 1) {
        int t = (tid >= off) ? sh[tid - off] : 0;
        __syncthreads();
        sh[tid] += t;
        __syncthreads();
    }
    if (tid == 1023) base_sh = atomicAdd(&g_ctr, sh[1023]);
    __syncthreads();
    if (i < n) {
        int rp = base_sh + sh[tid] - pc;
        g_rowptr[i] = rp;
        g_rowend[i] = rp + pc;
        g_invdeg[i] = 1.0f / (float)max(v, 1);
        for (int p = v; p < pc; ++p) g_col[rp + p] = n;   // dummy zero row
    }
}

// atomic-free scatter, 4 edges/thread
__global__ void k_scatter(const int* __restrict__ src, const int* __restrict__ dst, int E) {
    int t  = blockIdx.x * blockDim.x + threadIdx.x;
    int e4 = t * 4;
    if (e4 >= E) return;
    if (((E & 3) == 0) && e4 + 3 < E) {
        int4 d4 = ((const int4*)dst)[t];
        int4 p4 = ((const int4*)g_pos)[t];
        int4 s4 = ((const int4*)src)[t];
        g_col[g_rowptr[d4.x] + p4.x] = s4.x;
        g_col[g_rowptr[d4.y] + p4.y] = s4.y;
        g_col[g_rowptr[d4.z] + p4.z] = s4.z;
        g_col[g_rowptr[d4.w] + p4.w] = s4.w;
    } else {
        int lim = min(e4 + 4, E);
        for (int e = e4; e < lim; ++e)
            g_col[g_rowptr[dst[e]] + g_pos[e]] = src[e];
    }
}

// --------------------------- aggregate: m[i] = sum rows of (layer? h : xh)
// raw sums only (inv applied in gemm); max occupancy (8 blocks/SM, 32 regs)
__global__ __launch_bounds__(256, 8) void k_agg(int layer, int n) {
    int tid  = threadIdx.x;
    int lane = tid & 31, w = tid >> 5;
    int node = blockIdx.x * 8 + w;
    int g = lane >> 3, s = lane & 7;
    if (node >= n) return;

    const float4* Y = (const float4*)(layer ? g_h : g_xh);
    float acc[8];
    gather_row(Y, g_rowptr[node], g_rowend[node], g, s, acc);

    if (g == 0) {
        __half2 hh[4];
        hh[0] = __floats2half2_rn(acc[0], acc[1]);
        hh[1] = __floats2half2_rn(acc[2], acc[3]);
        hh[2] = __floats2half2_rn(acc[4], acc[5]);
        hh[3] = __floats2half2_rn(acc[6], acc[7]);
        *(float4*)&g_m[node * 64 + s * 8] = *(float4*)hh;
    }
}

// ------------- concat GEMM: out = [inv*m | Yin] @ [Wl; Wr] + b  (K = 128)
// layer 0: Yin = xh, out -> g_h (relu, fp16). layer 1: Yin = h, out -> Og (fp32).
__global__ __launch_bounds__(256) void k_gemm(const float* __restrict__ Wl,
                                              const float* __restrict__ Wr,
                                              const float* __restrict__ B,
                                              float* __restrict__ Og,
                                              int layer, int n) {
    __shared__ __half xs[64 * TSA];
    __shared__ __half ws[128 * TSB];
    __shared__ float  bs[64];

    int tid  = threadIdx.x;
    int row0 = blockIdx.x * 64;

    // B tile: rows 0-63 = Wl, rows 64-127 = Wr  (row-major [64,64] each)
    for (int t = tid; t < 2048; t += 256) {
        int r = t >> 4, c4 = (t & 15) << 2;
        const float* Wsrc = (r < 64) ? &Wl[r * 64 + c4] : &Wr[(r - 64) * 64 + c4];
        float4 v = *(const float4*)Wsrc;
        *(__half2*)&ws[r * TSB + c4]     = __floats2half2_rn(v.x, v.y);
        *(__half2*)&ws[r * TSB + c4 + 2] = __floats2half2_rn(v.z, v.w);
    }
    // A tile: cols 0-63 = inv*m, cols 64-127 = Yin (both fp16)
    const __half* Yin = layer ? g_h : g_xh;
    for (int t = tid; t < 1024; t += 256) {
        int r = t >> 4, cc = t & 15;
        int gr = row0 + r;
        float4 v = make_float4(0.f, 0.f, 0.f, 0.f);
        if (gr < n) {
            if (cc < 8) {
                v = *(const float4*)&g_m[gr * 64 + cc * 8];
                __half2 inv2 = __half2half2(__float2half_rn(g_invdeg[gr]));
                __half2* hv = (__half2*)&v;
                hv[0] = __hmul2(hv[0], inv2);
                hv[1] = __hmul2(hv[1], inv2);
                hv[2] = __hmul2(hv[2], inv2);
                hv[3] = __hmul2(hv[3], inv2);
            } else {
                v = *(const float4*)&Yin[gr * 64 + (cc - 8) * 8];
            }
        }
        *(float4*)&xs[r * TSA + cc * 8] = v;
    }
    if (tid < 64) bs[tid] = B[tid];
    // cleanup (last kernel in chain when layer==1)
    if (layer && tid < 64) {
        int nn = row0 + tid;
        if (nn < n) g_cnt[nn] = 0;
    }
    if (layer && blockIdx.x == 0 && tid == 0) g_ctr = 0;
    __syncthreads();

    int w = tid >> 5, l = tid & 31;
    int m0 = (w & 3) * 16;
    int nb = (w >> 2) * 32;

    float acc[4][4];
    #pragma unroll
    for (int j = 0; j < 4; ++j)
        #pragma unroll
        for (int q = 0; q < 4; ++q) acc[j][q] = 0.f;

    int ag = l >> 3, ar = l & 7;
    int arow = m0 + (ag & 1) * 8 + ar;
    int acol = (ag >> 1) * 8;
    int br   = (l & 7) + ((l >> 3) & 1) * 8;

    #pragma unroll
    for (int kc = 0; kc < 8; ++kc) {
        int k0 = kc * 16;
        unsigned a0, a1, a2, a3;
        ldsm_x4(a0, a1, a2, a3, smem_u32(&xs[arow * TSA + k0 + acol]));
        #pragma unroll
        for (int j = 0; j < 4; ++j) {
            unsigned b0, b1;
            ldsm_x2t(b0, b1, smem_u32(&ws[(k0 + br) * TSB + nb + j * 8]));
            mma16816(acc[j], a0, a1, a2, a3, b0, b1);
        }
    }

    int tr = l >> 2, tc = (l & 3) * 2;
    #pragma unroll
    for (int j = 0; j < 4; ++j) {
        int gc = nb + j * 8 + tc;
        float bx = bs[gc], by = bs[gc + 1];
        #pragma unroll
        for (int h = 0; h < 2; ++h) {
            int gr = row0 + m0 + tr + h * 8;
            if (gr < n) {
                float vx = acc[j][h * 2]     + bx;
                float vy = acc[j][h * 2 + 1] + by;
                if (layer == 0) {
                    *(__half2*)&g_h[gr * 64 + gc] =
                        __floats2half2_rn(fmaxf(vx, 0.f), fmaxf(vy, 0.f));
                } else {
                    *(float2*)&Og[gr * 64 + gc] = make_float2(vx, vy);
                }
            }
        }
    }
}

// ------------------------------------------------------------------- launch
extern "C" void kernel_launch(void* const* d_in, const int* in_sizes, int n_in,
                              void* d_out, int out_size) {
    const float* x   = (const float*)d_in[0];
    const int*   ei  = (const int*)d_in[1];
    const float* w1l = (const float*)d_in[2];
    const float* b1l = (const float*)d_in[3];
    const float* w1r = (const float*)d_in[4];
    const float* w2l = (const float*)d_in[5];
    const float* b2l = (const float*)d_in[6];
    const float* w2r = (const float*)d_in[7];
    float* out = (float*)d_out;

    int n = in_sizes[0] / F;
    int E = in_sizes[1] / 2;
    const int* src = ei;
    const int* dst = ei + E;

    int HB = (E + 1023) / 1024;              // hist blocks (4 edges/thread)
    int CB = (n * 8 + 255) / 256;            // convert blocks (8 floats/thread)
    int GB = (n + 63) / 64;                  // gemm blocks

    k_histprep<<<HB + CB, 256>>>(dst, E, HB, x, n);
    k_scan    <<<(n + 1023) / 1024, 1024>>>(n);
    k_scatter <<<(E / 4 + 255) / 256, 256>>>(src, dst, E);

    k_agg <<<(n + 7) / 8, 256>>>(0, n);                      // m = sum(xh)
    k_gemm<<<GB, 256>>>(w1l, w1r, b1l, nullptr, 0, n);       // h = relu([inv*m|xh]@W1+b1)
    k_agg <<<(n + 7) / 8, 256>>>(1, n);                      // m = sum(h)
    k_gemm<<<GB, 256>>>(w2l, w2r, b2l, out, 1, n);           // out = [inv*m|h]@W2+b2
}